// round 5
// baseline (speedup 1.0000x reference)
#include <cuda_runtime.h>
#include <math.h>

#define B_ 2
#define N_ 512
#define D_ 128
#define V_ 16
#define ROWS (B_*N_)

// scratch (allocation-free rule: __device__ globals)
__device__ float g_q  [ROWS*D_];   // q * invS
__device__ float g_k  [ROWS*D_];
__device__ float g_vv [ROWS*D_];
__device__ float g_qc [ROWS*10];   // qc[p]*invS for p=1..10
__device__ float g_bias[ROWS];     // (qc[0] + q.b_d2)*invS

__device__ __forceinline__ float geluf(float x){
    return 0.5f*x*(1.0f+erff(x*0.70710678118654752f));
}
// polynomial coefficients of gelu_fast(w*t+b) in powers of t (degree 10)
__device__ __forceinline__ void gelu_coeffs(float w, float b, float C[11]){
    const float K  = 0.3989422804014327f;
    const float c2 = K;
    const float c4 = K*-0.16666666666667f;
    const float c6 = K*0.025f;
    const float c8 = K*-2.9761904761905e-3f;
    const float c10= K*2.8935185185185e-4f;
    float wp[11], bp[11];
    wp[0]=1.f; bp[0]=1.f;
    #pragma unroll
    for(int t=1;t<11;t++){ wp[t]=wp[t-1]*w; bp[t]=bp[t-1]*b; }
    #pragma unroll
    for(int p=0;p<11;p++) C[p]=0.f;
    C[0] += 0.5f*b; C[1] += 0.5f*w;
    const float B2[3]={1,2,1};
    const float B4[5]={1,4,6,4,1};
    const float B6[7]={1,6,15,20,15,6,1};
    const float B8[9]={1,8,28,56,70,56,28,8,1};
    const float B10[11]={1,10,45,120,210,252,210,120,45,10,1};
    #pragma unroll
    for(int p=0;p<=2;p++)  C[p] += c2 *B2[p] *wp[p]*bp[2-p];
    #pragma unroll
    for(int p=0;p<=4;p++)  C[p] += c4 *B4[p] *wp[p]*bp[4-p];
    #pragma unroll
    for(int p=0;p<=6;p++)  C[p] += c6 *B6[p] *wp[p]*bp[6-p];
    #pragma unroll
    for(int p=0;p<=8;p++)  C[p] += c8 *B8[p] *wp[p]*bp[8-p];
    #pragma unroll
    for(int p=0;p<=10;p++) C[p] += c10*B10[p]*wp[p]*bp[10-p];
}
__device__ __forceinline__ float warpSum(float v){
    #pragma unroll
    for(int o=16;o;o>>=1) v += __shfl_down_sync(0xffffffffu, v, o);
    return v;
}
__device__ __forceinline__ float blockSum(float v, float* red){
    int w = threadIdx.x>>5, l = threadIdx.x&31;
    v = warpSum(v);
    if(l==0) red[w]=v;
    __syncthreads();
    if(threadIdx.x==0) red[0] = red[0]+red[1]+red[2]+red[3];
    __syncthreads();
    float r = red[0];
    __syncthreads();
    return r;
}

// ---------------- Kernel A: LN + q/k/v + qc moments coefficients ----------
__global__ void __launch_bounds__(128) prep_kernel(
    const float* __restrict__ scalar,
    const float* __restrict__ w_q, const float* __restrict__ b_q,
    const float* __restrict__ w_k, const float* __restrict__ b_k,
    const float* __restrict__ w_v, const float* __restrict__ b_v,
    const float* __restrict__ w_d1, const float* __restrict__ b_d1,
    const float* __restrict__ w_d2, const float* __restrict__ b_d2,
    const float* __restrict__ g_s, const float* __restrict__ be_s)
{
    __shared__ float ssn[D_], sq[D_], red[4];
    __shared__ float sWq[4][12];
    const int row = blockIdx.x;
    const int d = threadIdx.x;
    const int warp = d>>5, lane = d&31;
    const float invS = 0.0883883476483184f; // 1/sqrt(128)

    float x = scalar[row*D_+d];
    float m  = blockSum(x, red)*(1.0f/D_);
    float dv = x - m;
    float var= blockSum(dv*dv, red)*(1.0f/D_);
    float sn = dv*rsqrtf(var+1e-5f)*g_s[d] + be_s[d];
    ssn[d]=sn;
    __syncthreads();

    // q/k/v matvec: 12 accumulators, batched loads
    float qa[4]={0,0,0,0}, ka[4]={0,0,0,0}, va[4]={0,0,0,0};
    #pragma unroll 4
    for(int e=0;e<D_;e+=4){
        float s0=ssn[e], s1=ssn[e+1], s2=ssn[e+2], s3=ssn[e+3];
        float wq0=w_q[(e+0)*D_+d], wq1=w_q[(e+1)*D_+d], wq2=w_q[(e+2)*D_+d], wq3=w_q[(e+3)*D_+d];
        float wk0=w_k[(e+0)*D_+d], wk1=w_k[(e+1)*D_+d], wk2=w_k[(e+2)*D_+d], wk3=w_k[(e+3)*D_+d];
        float wv0=w_v[(e+0)*D_+d], wv1=w_v[(e+1)*D_+d], wv2=w_v[(e+2)*D_+d], wv3=w_v[(e+3)*D_+d];
        qa[0]=fmaf(s0,wq0,qa[0]); qa[1]=fmaf(s1,wq1,qa[1]); qa[2]=fmaf(s2,wq2,qa[2]); qa[3]=fmaf(s3,wq3,qa[3]);
        ka[0]=fmaf(s0,wk0,ka[0]); ka[1]=fmaf(s1,wk1,ka[1]); ka[2]=fmaf(s2,wk2,ka[2]); ka[3]=fmaf(s3,wk3,ka[3]);
        va[0]=fmaf(s0,wv0,va[0]); va[1]=fmaf(s1,wv1,va[1]); va[2]=fmaf(s2,wv2,va[2]); va[3]=fmaf(s3,wv3,va[3]);
    }
    float q = (qa[0]+qa[1])+(qa[2]+qa[3])+b_q[d];
    g_q [row*D_+d]=q*invS;
    g_k [row*D_+d]=(ka[0]+ka[1])+(ka[2]+ka[3])+b_k[d];
    g_vv[row*D_+d]=(va[0]+va[1])+(va[2]+va[3])+b_v[d];
    sq[d]=q;
    __syncthreads();

    // qd[e] = sum_d w_d2[e,d]*q[d]  (thread index = e)
    float a0=0,a1=0,a2=0,a3=0;
    #pragma unroll 4
    for(int e2=0;e2<D_;e2+=4){
        a0 = fmaf(sq[e2+0], w_d2[d*D_+e2+0], a0);
        a1 = fmaf(sq[e2+1], w_d2[d*D_+e2+1], a1);
        a2 = fmaf(sq[e2+2], w_d2[d*D_+e2+2], a2);
        a3 = fmaf(sq[e2+3], w_d2[d*D_+e2+3], a3);
    }
    float qd = (a0+a1)+(a2+a3);

    float C[11];
    gelu_coeffs(w_d1[d], b_d1[d], C);

    // 12 interleaved warp reductions (independent shfl chains)
    float t[12];
    #pragma unroll
    for(int p=0;p<11;p++) t[p]=qd*C[p];
    t[11]=q*b_d2[d];
    #pragma unroll
    for(int o=16;o;o>>=1){
        #pragma unroll
        for(int p=0;p<12;p++) t[p] += __shfl_down_sync(0xffffffffu, t[p], o);
    }
    if(lane==0){
        #pragma unroll
        for(int p=0;p<12;p++) sWq[warp][p]=t[p];
    }
    __syncthreads();
    if(d==0){
        float qc0 = sWq[0][0]+sWq[1][0]+sWq[2][0]+sWq[3][0];
        float qdb = sWq[0][11]+sWq[1][11]+sWq[2][11]+sWq[3][11];
        g_bias[row] = (qc0+qdb)*invS;
    } else if(d<11){
        float qcp = sWq[0][d]+sWq[1][d]+sWq[2][d]+sWq[3][d];
        g_qc[row*10 + (d-1)] = qcp*invS;
    }
}

// ---------------- Kernel B: fused attention + all epilogues, one row/block --
__global__ void __launch_bounds__(128) main_kernel(
    const float* __restrict__ scalar, const float* __restrict__ vector,
    const float* __restrict__ coords,
    const float* __restrict__ w_d1, const float* __restrict__ b_d1,
    const float* __restrict__ w_d2, const float* __restrict__ b_d2,
    const float* __restrict__ w_g,  const float* __restrict__ b_g,
    const float* __restrict__ w_o,  const float* __restrict__ b_o,
    const float* __restrict__ w_f1, const float* __restrict__ b_f1,
    const float* __restrict__ w_f2, const float* __restrict__ b_f2,
    const float* __restrict__ w_vo, const float* __restrict__ b_vo,
    const float* __restrict__ g_s,  const float* __restrict__ be_s,
    const float* __restrict__ g_v_, const float* __restrict__ be_v,
    float* __restrict__ out_scalar, float* __restrict__ out_vector)
{
    __shared__ float sq[D_];
    __shared__ float scoord[N_*3];
    __shared__ float sdist[N_], srd[N_], slog[N_];
    __shared__ float sVm[4][D_];
    __shared__ float sMm[4][10];
    __shared__ float sMn[10];
    __shared__ float sSum[4];
    __shared__ float sH[D_], sbuf[D_], sscal[D_], shn[D_], sf[2*D_];
    __shared__ float svagg2[96], sdirp[24], sdir[3], sgate[V_], sagg[48], svagg[48];
    __shared__ float red[4];

    const int row  = blockIdx.x;
    const int b    = row >> 9;
    const int i    = row & (N_-1);
    const int tid  = threadIdx.x;
    const int warp = tid>>5, lane = tid&31;
    const int half = lane>>4, hl = lane&15;

    sq[tid] = g_q[row*D_+tid];
    const float* cb = coords + (size_t)b*N_*3;
    for(int t=tid; t<N_*3; t+=128) scoord[t]=cb[t];
    const float biasRow = g_bias[row];
    __syncthreads();

    const float ci0 = scoord[i*3+0], ci1 = scoord[i*3+1], ci2 = scoord[i*3+2];

    // ---- pre-pass: all 512 dists (+ reciprocal) ----
    for(int j=tid; j<N_; j+=128){
        float dx = ci0 - scoord[j*3+0];
        float dy = ci1 - scoord[j*3+1];
        float dz = ci2 - scoord[j*3+2];
        float dist = sqrtf(fmaf(dx,dx,fmaf(dy,dy,dz*dz)));
        sdist[j] = dist;
        srd[j]   = __fdividef(1.0f, fmaxf(dist, 1e-6f));
    }
    __syncthreads();

    const float* kb   = g_k  + (size_t)b*N_*D_;
    const float* vvb  = g_vv + (size_t)b*N_*D_;
    const float* vecb = vector + (size_t)b*N_*3*V_;

    // per-lane constants: d = hl*8 + c, moment index p = hl+1 (hl<10)
    float qr[8];
    {
        const float4* p=(const float4*)sq;
        float4 a=p[hl*2], bb=p[hl*2+1];
        qr[0]=a.x;qr[1]=a.y;qr[2]=a.z;qr[3]=a.w; qr[4]=bb.x;qr[5]=bb.y;qr[6]=bb.z;qr[7]=bb.w;
    }
    const int pidx = hl+1;
    const bool u1 = (pidx&1), u2 = (pidx&2), u4 = (pidx&4), u8 = (pidx&8);
    const float qcl = (hl<10) ? g_qc[row*10+hl] : 0.0f;

    // ---- single fused pass, 4x unrolled, loads batched up-front ----
    float Vc[8]={0,0,0,0,0,0,0,0};
    float Ml = 0.0f, sacc = 0.0f;

    for(int base = warp*2; base < N_; base += 32){
        int j0 = base    + half;
        int j1 = base+8  + half;
        int j2 = base+16 + half;
        int j3 = base+24 + half;
        float dist0 = sdist[j0], dist1 = sdist[j1], dist2 = sdist[j2], dist3 = sdist[j3];

        const float4* k0 = (const float4*)(kb + (size_t)j0*D_);
        const float4* k1 = (const float4*)(kb + (size_t)j1*D_);
        const float4* k2 = (const float4*)(kb + (size_t)j2*D_);
        const float4* k3 = (const float4*)(kb + (size_t)j3*D_);
        const float4* v0 = (const float4*)(vvb + (size_t)j0*D_);
        const float4* v1 = (const float4*)(vvb + (size_t)j1*D_);
        const float4* v2 = (const float4*)(vvb + (size_t)j2*D_);
        const float4* v3 = (const float4*)(vvb + (size_t)j3*D_);
        // batch all 16 loads
        float4 K0a=k0[hl*2], K0b=k0[hl*2+1], K1a=k1[hl*2], K1b=k1[hl*2+1];
        float4 K2a=k2[hl*2], K2b=k2[hl*2+1], K3a=k3[hl*2], K3b=k3[hl*2+1];
        float4 V0a=v0[hl*2], V0b=v0[hl*2+1], V1a=v1[hl*2], V1b=v1[hl*2+1];
        float4 V2a=v2[hl*2], V2b=v2[hl*2+1], V3a=v3[hl*2], V3b=v3[hl*2+1];

        // ---- sub 0 ----
        {
            float d2=dist0*dist0, d4=d2*d2, d8=d4*d4;
            float pw=(u1?dist0:1.0f); pw*=(u2?d2:1.0f); pw*=(u4?d4:1.0f); pw*=(u8?d8:1.0f);
            float p = qcl*pw;
            p=fmaf(qr[0],K0a.x,p); p=fmaf(qr[1],K0a.y,p); p=fmaf(qr[2],K0a.z,p); p=fmaf(qr[3],K0a.w,p);
            p=fmaf(qr[4],K0b.x,p); p=fmaf(qr[5],K0b.y,p); p=fmaf(qr[6],K0b.z,p); p=fmaf(qr[7],K0b.w,p);
            p += __shfl_xor_sync(0xffffffffu,p,8); p += __shfl_xor_sync(0xffffffffu,p,4);
            p += __shfl_xor_sync(0xffffffffu,p,2); p += __shfl_xor_sync(0xffffffffu,p,1);
            float e = __expf(p + biasRow);
            if(hl==0) slog[j0]=e;
            sacc += e; Ml = fmaf(e,pw,Ml);
            Vc[0]=fmaf(e,V0a.x,Vc[0]); Vc[1]=fmaf(e,V0a.y,Vc[1]); Vc[2]=fmaf(e,V0a.z,Vc[2]); Vc[3]=fmaf(e,V0a.w,Vc[3]);
            Vc[4]=fmaf(e,V0b.x,Vc[4]); Vc[5]=fmaf(e,V0b.y,Vc[5]); Vc[6]=fmaf(e,V0b.z,Vc[6]); Vc[7]=fmaf(e,V0b.w,Vc[7]);
        }
        // ---- sub 1 ----
        {
            float d2=dist1*dist1, d4=d2*d2, d8=d4*d4;
            float pw=(u1?dist1:1.0f); pw*=(u2?d2:1.0f); pw*=(u4?d4:1.0f); pw*=(u8?d8:1.0f);
            float p = qcl*pw;
            p=fmaf(qr[0],K1a.x,p); p=fmaf(qr[1],K1a.y,p); p=fmaf(qr[2],K1a.z,p); p=fmaf(qr[3],K1a.w,p);
            p=fmaf(qr[4],K1b.x,p); p=fmaf(qr[5],K1b.y,p); p=fmaf(qr[6],K1b.z,p); p=fmaf(qr[7],K1b.w,p);
            p += __shfl_xor_sync(0xffffffffu,p,8); p += __shfl_xor_sync(0xffffffffu,p,4);
            p += __shfl_xor_sync(0xffffffffu,p,2); p += __shfl_xor_sync(0xffffffffu,p,1);
            float e = __expf(p + biasRow);
            if(hl==0) slog[j1]=e;
            sacc += e; Ml = fmaf(e,pw,Ml);
            Vc[0]=fmaf(e,V1a.x,Vc[0]); Vc[1]=fmaf(e,V1a.y,Vc[1]); Vc[2]=fmaf(e,V1a.z,Vc[2]); Vc[3]=fmaf(e,V1a.w,Vc[3]);
            Vc[4]=fmaf(e,V1b.x,Vc[4]); Vc[5]=fmaf(e,V1b.y,Vc[5]); Vc[6]=fmaf(e,V1b.z,Vc[6]); Vc[7]=fmaf(e,V1b.w,Vc[7]);
        }
        // ---- sub 2 ----
        {
            float d2=dist2*dist2, d4=d2*d2, d8=d4*d4;
            float pw=(u1?dist2:1.0f); pw*=(u2?d2:1.0f); pw*=(u4?d4:1.0f); pw*=(u8?d8:1.0f);
            float p = qcl*pw;
            p=fmaf(qr[0],K2a.x,p); p=fmaf(qr[1],K2a.y,p); p=fmaf(qr[2],K2a.z,p); p=fmaf(qr[3],K2a.w,p);
            p=fmaf(qr[4],K2b.x,p); p=fmaf(qr[5],K2b.y,p); p=fmaf(qr[6],K2b.z,p); p=fmaf(qr[7],K2b.w,p);
            p += __shfl_xor_sync(0xffffffffu,p,8); p += __shfl_xor_sync(0xffffffffu,p,4);
            p += __shfl_xor_sync(0xffffffffu,p,2); p += __shfl_xor_sync(0xffffffffu,p,1);
            float e = __expf(p + biasRow);
            if(hl==0) slog[j2]=e;
            sacc += e; Ml = fmaf(e,pw,Ml);
            Vc[0]=fmaf(e,V2a.x,Vc[0]); Vc[1]=fmaf(e,V2a.y,Vc[1]); Vc[2]=fmaf(e,V2a.z,Vc[2]); Vc[3]=fmaf(e,V2a.w,Vc[3]);
            Vc[4]=fmaf(e,V2b.x,Vc[4]); Vc[5]=fmaf(e,V2b.y,Vc[5]); Vc[6]=fmaf(e,V2b.z,Vc[6]); Vc[7]=fmaf(e,V2b.w,Vc[7]);
        }
        // ---- sub 3 ----
        {
            float d2=dist3*dist3, d4=d2*d2, d8=d4*d4;
            float pw=(u1?dist3:1.0f); pw*=(u2?d2:1.0f); pw*=(u4?d4:1.0f); pw*=(u8?d8:1.0f);
            float p = qcl*pw;
            p=fmaf(qr[0],K3a.x,p); p=fmaf(qr[1],K3a.y,p); p=fmaf(qr[2],K3a.z,p); p=fmaf(qr[3],K3a.w,p);
            p=fmaf(qr[4],K3b.x,p); p=fmaf(qr[5],K3b.y,p); p=fmaf(qr[6],K3b.z,p); p=fmaf(qr[7],K3b.w,p);
            p += __shfl_xor_sync(0xffffffffu,p,8); p += __shfl_xor_sync(0xffffffffu,p,4);
            p += __shfl_xor_sync(0xffffffffu,p,2); p += __shfl_xor_sync(0xffffffffu,p,1);
            float e = __expf(p + biasRow);
            if(hl==0) slog[j3]=e;
            sacc += e; Ml = fmaf(e,pw,Ml);
            Vc[0]=fmaf(e,V3a.x,Vc[0]); Vc[1]=fmaf(e,V3a.y,Vc[1]); Vc[2]=fmaf(e,V3a.z,Vc[2]); Vc[3]=fmaf(e,V3a.w,Vc[3]);
            Vc[4]=fmaf(e,V3b.x,Vc[4]); Vc[5]=fmaf(e,V3b.y,Vc[5]); Vc[6]=fmaf(e,V3b.z,Vc[6]); Vc[7]=fmaf(e,V3b.w,Vc[7]);
        }
    }

    // merge halves within warp
    #pragma unroll
    for(int c=0;c<8;c++) Vc[c] += __shfl_xor_sync(0xffffffffu, Vc[c], 16);
    sacc += __shfl_xor_sync(0xffffffffu, sacc, 16);
    Ml   += __shfl_xor_sync(0xffffffffu, Ml, 16);
    if(half==0){
        #pragma unroll
        for(int c=0;c<8;c++) sVm[warp][hl*8+c]=Vc[c];
        if(hl<10) sMm[warp][hl]=Ml;
    }
    if(lane==0) sSum[warp]=sacc;
    __syncthreads();

    // merge warps + normalize (slog stays raw; inv folded at consumers)
    const float inv = 1.0f/(sSum[0]+sSum[1]+sSum[2]+sSum[3]);
    float Vd = (sVm[0][tid]+sVm[1][tid]+sVm[2][tid]+sVm[3][tid])*inv;
    if(tid<10) sMn[tid] = (sMm[0][tid]+sMm[1][tid]+sMm[2][tid]+sMm[3][tid])*inv;
    __syncthreads();

    // ---- H reconstruction from moments ----
    {
        float C[11];
        gelu_coeffs(w_d1[tid], b_d1[tid], C);
        float Hd = C[0];
        #pragma unroll
        for(int p=1;p<11;p++) Hd = fmaf(C[p], sMn[p-1], Hd);
        sH[tid]=Hd;
    }

    // ---- vector aggregation (96 thr) + direction aggregation (24 thr) ----
    if(tid < 96){
        const int t48 = (tid<48)?tid:(tid-48);
        const int j0  = (tid<48)?0:256;
        float a0=0,a1=0;
        #pragma unroll 4
        for(int j=j0;j<j0+256;j+=2){
            a0 = fmaf(slog[j],   vecb[(size_t)j*48+t48],     a0);
            a1 = fmaf(slog[j+1], vecb[(size_t)(j+1)*48+t48], a1);
        }
        svagg2[tid]=(a0+a1)*inv;
    } else if(tid < 120){
        const int idx = tid-96, c = idx>>3, g = idx&7;
        const float cic = scoord[i*3+c];
        float acc=0.0f;
        for(int j=g;j<N_;j+=8){
            acc = fmaf(slog[j]*srd[j], cic - scoord[j*3+c], acc);
        }
        sdirp[idx]=acc*inv;
    }
    __syncthreads();
    if(tid<48) svagg[tid]=svagg2[tid]+svagg2[tid+48];
    if(tid<3){
        float a=0;
        #pragma unroll
        for(int g=0;g<8;g++) a+=sdirp[tid*8+g];
        sdir[tid]=a;
    }

    // ---- upd = attn@v + H@w_d2 + b_d2 ----
    {
        float u0=0,u1=0,u2=0,u3=0;
        #pragma unroll 4
        for(int e=0;e<D_;e+=4){
            u0 = fmaf(sH[e+0], w_d2[(e+0)*D_+tid], u0);
            u1 = fmaf(sH[e+1], w_d2[(e+1)*D_+tid], u1);
            u2 = fmaf(sH[e+2], w_d2[(e+2)*D_+tid], u2);
            u3 = fmaf(sH[e+3], w_d2[(e+3)*D_+tid], u3);
        }
        sbuf[tid] = Vd + b_d2[tid] + ((u0+u1)+(u2+u3));
    }
    __syncthreads();

    // ---- scalar1 = scalar + upd@w_o + b_o ----
    float s1;
    {
        float u0=0,u1=0,u2=0,u3=0;
        #pragma unroll 4
        for(int e=0;e<D_;e+=4){
            u0 = fmaf(sbuf[e+0], w_o[(e+0)*D_+tid], u0);
            u1 = fmaf(sbuf[e+1], w_o[(e+1)*D_+tid], u1);
            u2 = fmaf(sbuf[e+2], w_o[(e+2)*D_+tid], u2);
            u3 = fmaf(sbuf[e+3], w_o[(e+3)*D_+tid], u3);
        }
        s1 = scalar[row*D_+tid] + b_o[tid] + ((u0+u1)+(u2+u3));
    }
    sscal[tid]=s1;

    // ---- LN ----
    float m  = blockSum(s1, red)*(1.0f/D_);
    float dv = s1 - m;
    float var= blockSum(dv*dv, red)*(1.0f/D_);
    float hn = dv*rsqrtf(var+1e-5f)*g_s[tid] + be_s[tid];
    shn[tid]=hn;
    __syncthreads();

    // ---- FFN layer 1 ----
    #pragma unroll
    for(int h2=0; h2<2; h2++){
        int m2 = tid + h2*128;
        float u0=0,u1=0,u2=0,u3=0;
        #pragma unroll 4
        for(int e=0;e<D_;e+=4){
            u0 = fmaf(shn[e+0], w_f1[(e+0)*2*D_+m2], u0);
            u1 = fmaf(shn[e+1], w_f1[(e+1)*2*D_+m2], u1);
            u2 = fmaf(shn[e+2], w_f1[(e+2)*2*D_+m2], u2);
            u3 = fmaf(shn[e+3], w_f1[(e+3)*2*D_+m2], u3);
        }
        sf[m2]=geluf(b_f1[m2] + (u0+u1)+(u2+u3));
    }
    __syncthreads();

    // ---- FFN layer 2 ----
    float s2;
    {
        float u0=0,u1=0,u2=0,u3=0;
        #pragma unroll 4
        for(int m2=0;m2<2*D_;m2+=4){
            u0 = fmaf(sf[m2+0], w_f2[(m2+0)*D_+tid], u0);
            u1 = fmaf(sf[m2+1], w_f2[(m2+1)*D_+tid], u1);
            u2 = fmaf(sf[m2+2], w_f2[(m2+2)*D_+tid], u2);
            u3 = fmaf(sf[m2+3], w_f2[(m2+3)*D_+tid], u3);
        }
        s2 = sscal[tid] + b_f2[tid] + ((u0+u1)+(u2+u3));
    }
    out_scalar[row*D_+tid] = s2;
    __syncthreads();
    sscal[tid] = s2;
    __syncthreads();

    // ---- gate ----
    if(tid<V_){
        float u0=0,u1=0,u2=0,u3=0;
        #pragma unroll 4
        for(int d2=0;d2<D_;d2+=4){
            u0 = fmaf(sscal[d2+0], w_g[(d2+0)*V_+tid], u0);
            u1 = fmaf(sscal[d2+1], w_g[(d2+1)*V_+tid], u1);
            u2 = fmaf(sscal[d2+2], w_g[(d2+2)*V_+tid], u2);
            u3 = fmaf(sscal[d2+3], w_g[(d2+3)*V_+tid], u3);
        }
        float a = b_g[tid] + (u0+u1)+(u2+u3);
        sgate[tid] = 1.0f/(1.0f+__expf(-a));
    }
    __syncthreads();

    // ---- agg, LN over V, proj, vector residual ----
    if(tid<48){
        int c = tid>>4, vv = tid&15;
        sagg[tid] = svagg[tid] + sdir[c]*sgate[vv];
    }
    __syncthreads();
    if(tid<48){
        int c = tid>>4, vv = tid&15;
        float m2=0.0f;
        #pragma unroll
        for(int u=0;u<V_;u++) m2 += sagg[c*V_+u];
        m2 *= (1.0f/V_);
        float var2=0.0f;
        #pragma unroll
        for(int u=0;u<V_;u++){ float d3=sagg[c*V_+u]-m2; var2 += d3*d3; }
        var2 *= (1.0f/V_);
        float invr = rsqrtf(var2+1e-5f);
        float acc = b_vo[vv];
        #pragma unroll
        for(int u=0;u<V_;u++){
            float lnu = (sagg[c*V_+u]-m2)*invr*g_v_[u] + be_v[u];
            acc = fmaf(lnu, w_vo[u*V_+vv], acc);
        }
        out_vector[row*3*V_+tid] = vecb[(size_t)i*3*V_+tid] + acc;
    }
}

extern "C" void kernel_launch(void* const* d_in, const int* in_sizes, int n_in,
                              void* d_out, int out_size)
{
    const float* scalar = (const float*)d_in[0];
    const float* vector = (const float*)d_in[1];
    const float* coords = (const float*)d_in[2];
    const float* w_q  = (const float*)d_in[3];  const float* b_q  = (const float*)d_in[4];
    const float* w_k  = (const float*)d_in[5];  const float* b_k  = (const float*)d_in[6];
    const float* w_v  = (const float*)d_in[7];  const float* b_v  = (const float*)d_in[8];
    const float* w_d1 = (const float*)d_in[9];  const float* b_d1 = (const float*)d_in[10];
    const float* w_d2 = (const float*)d_in[11]; const float* b_d2 = (const float*)d_in[12];
    const float* w_g  = (const float*)d_in[13]; const float* b_g  = (const float*)d_in[14];
    const float* w_o  = (const float*)d_in[15]; const float* b_o  = (const float*)d_in[16];
    const float* w_f1 = (const float*)d_in[17]; const float* b_f1 = (const float*)d_in[18];
    const float* w_f2 = (const float*)d_in[19]; const float* b_f2 = (const float*)d_in[20];
    const float* w_vo = (const float*)d_in[21]; const float* b_vo = (const float*)d_in[22];
    const float* g_s  = (const float*)d_in[23]; const float* be_s = (const float*)d_in[24];
    const float* g_v  = (const float*)d_in[25]; const float* be_v = (const float*)d_in[26];

    float* out = (float*)d_out;
    float* out_scalar = out;
    float* out_vector = out + (size_t)ROWS*D_;

    prep_kernel<<<ROWS,128>>>(scalar, w_q,b_q, w_k,b_k, w_v,b_v,
                              w_d1,b_d1, w_d2,b_d2, g_s,be_s);
    main_kernel<<<ROWS,128>>>(scalar, vector, coords,
                              w_d1,b_d1, w_d2,b_d2, w_g,b_g, w_o,b_o,
                              w_f1,b_f1, w_f2,b_f2, w_vo,b_vo,
                              g_s,be_s, g_v,be_v,
                              out_scalar, out_vector);
}

// round 6
// speedup vs baseline: 1.0591x; 1.0591x over previous
#include <cuda_runtime.h>
#include <math.h>

#define B_ 2
#define N_ 512
#define D_ 128
#define V_ 16
#define ROWS (B_*N_)

// scratch (allocation-free rule: __device__ globals)
__device__ float g_q  [ROWS*D_];   // q * invS
__device__ float g_k  [ROWS*D_];
__device__ float g_vv [ROWS*D_];
__device__ float g_qc [ROWS*10];   // qc[p]*invS for p=1..10
__device__ float g_bias[ROWS];     // (qc[0] + q.b_d2)*invS

__device__ __forceinline__ float geluf(float x){
    return 0.5f*x*(1.0f+erff(x*0.70710678118654752f));
}
// polynomial coefficients of gelu_fast(w*t+b) in powers of t (degree 10)
__device__ __forceinline__ void gelu_coeffs(float w, float b, float C[11]){
    const float K  = 0.3989422804014327f;
    const float c2 = K;
    const float c4 = K*-0.16666666666667f;
    const float c6 = K*0.025f;
    const float c8 = K*-2.9761904761905e-3f;
    const float c10= K*2.8935185185185e-4f;
    float wp[11], bp[11];
    wp[0]=1.f; bp[0]=1.f;
    #pragma unroll
    for(int t=1;t<11;t++){ wp[t]=wp[t-1]*w; bp[t]=bp[t-1]*b; }
    #pragma unroll
    for(int p=0;p<11;p++) C[p]=0.f;
    C[0] += 0.5f*b; C[1] += 0.5f*w;
    const float B2[3]={1,2,1};
    const float B4[5]={1,4,6,4,1};
    const float B6[7]={1,6,15,20,15,6,1};
    const float B8[9]={1,8,28,56,70,56,28,8,1};
    const float B10[11]={1,10,45,120,210,252,210,120,45,10,1};
    #pragma unroll
    for(int p=0;p<=2;p++)  C[p] += c2 *B2[p] *wp[p]*bp[2-p];
    #pragma unroll
    for(int p=0;p<=4;p++)  C[p] += c4 *B4[p] *wp[p]*bp[4-p];
    #pragma unroll
    for(int p=0;p<=6;p++)  C[p] += c6 *B6[p] *wp[p]*bp[6-p];
    #pragma unroll
    for(int p=0;p<=8;p++)  C[p] += c8 *B8[p] *wp[p]*bp[8-p];
    #pragma unroll
    for(int p=0;p<=10;p++) C[p] += c10*B10[p]*wp[p]*bp[10-p];
}
__device__ __forceinline__ float warpSum(float v){
    #pragma unroll
    for(int o=16;o;o>>=1) v += __shfl_down_sync(0xffffffffu, v, o);
    return v;
}
// 128-thread block reduction (prep kernel)
__device__ __forceinline__ float blockSum(float v, float* red){
    int w = threadIdx.x>>5, l = threadIdx.x&31;
    v = warpSum(v);
    if(l==0) red[w]=v;
    __syncthreads();
    if(threadIdx.x==0) red[0] = red[0]+red[1]+red[2]+red[3];
    __syncthreads();
    float r = red[0];
    __syncthreads();
    return r;
}
// 256-thread block reduction (main kernel)
__device__ __forceinline__ float blockSum256(float v, float* red){
    int w = threadIdx.x>>5, l = threadIdx.x&31;
    v = warpSum(v);
    if(l==0) red[w]=v;
    __syncthreads();
    if(threadIdx.x==0){
        float s = 0.f;
        #pragma unroll
        for(int k=0;k<8;k++) s += red[k];
        red[0]=s;
    }
    __syncthreads();
    float r = red[0];
    __syncthreads();
    return r;
}

// ---------------- Kernel A: LN + q/k/v + qc moments coefficients (R4) -------
__global__ void __launch_bounds__(128) prep_kernel(
    const float* __restrict__ scalar,
    const float* __restrict__ w_q, const float* __restrict__ b_q,
    const float* __restrict__ w_k, const float* __restrict__ b_k,
    const float* __restrict__ w_v, const float* __restrict__ b_v,
    const float* __restrict__ w_d1, const float* __restrict__ b_d1,
    const float* __restrict__ w_d2, const float* __restrict__ b_d2,
    const float* __restrict__ g_s, const float* __restrict__ be_s)
{
    __shared__ float ssn[D_], sq[D_], red[4];
    __shared__ float sWq[4][12];
    const int row = blockIdx.x;
    const int d = threadIdx.x;
    const int warp = d>>5, lane = d&31;
    const float invS = 0.0883883476483184f; // 1/sqrt(128)

    float x = scalar[row*D_+d];
    float m  = blockSum(x, red)*(1.0f/D_);
    float dv = x - m;
    float var= blockSum(dv*dv, red)*(1.0f/D_);
    float sn = dv*rsqrtf(var+1e-5f)*g_s[d] + be_s[d];
    ssn[d]=sn;
    __syncthreads();

    float q0=0,q1=0,k0=0,k1=0,v0=0,v1=0;
    #pragma unroll 4
    for(int e=0;e<D_;e+=2){
        float s0 = ssn[e], s1 = ssn[e+1];
        q0 = fmaf(s0, w_q[e*D_+d], q0);      q1 = fmaf(s1, w_q[(e+1)*D_+d], q1);
        k0 = fmaf(s0, w_k[e*D_+d], k0);      k1 = fmaf(s1, w_k[(e+1)*D_+d], k1);
        v0 = fmaf(s0, w_v[e*D_+d], v0);      v1 = fmaf(s1, w_v[(e+1)*D_+d], v1);
    }
    float q = q0+q1+b_q[d];
    g_q [row*D_+d]=q*invS;
    g_k [row*D_+d]=k0+k1+b_k[d];
    g_vv[row*D_+d]=v0+v1+b_v[d];
    sq[d]=q;
    __syncthreads();

    float a0=0,a1=0,a2=0,a3=0;
    #pragma unroll 4
    for(int e2=0;e2<D_;e2+=4){
        a0 = fmaf(sq[e2+0], w_d2[d*D_+e2+0], a0);
        a1 = fmaf(sq[e2+1], w_d2[d*D_+e2+1], a1);
        a2 = fmaf(sq[e2+2], w_d2[d*D_+e2+2], a2);
        a3 = fmaf(sq[e2+3], w_d2[d*D_+e2+3], a3);
    }
    float qd = (a0+a1)+(a2+a3);

    float C[11];
    gelu_coeffs(w_d1[d], b_d1[d], C);

    #pragma unroll
    for(int p=0;p<11;p++){
        float t = warpSum(qd*C[p]);
        if(lane==0) sWq[warp][p]=t;
    }
    {
        float t = warpSum(q*b_d2[d]);
        if(lane==0) sWq[warp][11]=t;
    }
    __syncthreads();
    if(d==0){
        float qc0 = sWq[0][0]+sWq[1][0]+sWq[2][0]+sWq[3][0];
        float qdb = sWq[0][11]+sWq[1][11]+sWq[2][11]+sWq[3][11];
        g_bias[row] = (qc0+qdb)*invS;
    } else if(d<11){
        float qcp = sWq[0][d]+sWq[1][d]+sWq[2][d]+sWq[3][d];
        g_qc[row*10 + (d-1)] = qcp*invS;
    }
}

// ---------------- Kernel B: fused attention + epilogues, 256 thr/row --------
__global__ void __launch_bounds__(256, 5) main_kernel(
    const float* __restrict__ scalar, const float* __restrict__ vector,
    const float* __restrict__ coords,
    const float* __restrict__ w_d1, const float* __restrict__ b_d1,
    const float* __restrict__ w_d2, const float* __restrict__ b_d2,
    const float* __restrict__ w_g,  const float* __restrict__ b_g,
    const float* __restrict__ w_o,  const float* __restrict__ b_o,
    const float* __restrict__ w_f1, const float* __restrict__ b_f1,
    const float* __restrict__ w_f2, const float* __restrict__ b_f2,
    const float* __restrict__ w_vo, const float* __restrict__ b_vo,
    const float* __restrict__ g_s,  const float* __restrict__ be_s,
    const float* __restrict__ g_v_, const float* __restrict__ be_v,
    float* __restrict__ out_scalar, float* __restrict__ out_vector)
{
    __shared__ float sq[D_];
    __shared__ float scoord[N_*3];
    __shared__ float sdist[N_], srd[N_], slog[N_];
    __shared__ float sVm[8][D_];
    __shared__ float sMm[8][10];
    __shared__ float sMn[10];
    __shared__ float sSum[8];
    __shared__ float sH[D_], sbuf[D_], sscal[D_], shn[D_], sf[2*D_];
    __shared__ float spart[256];
    __shared__ float svagg4[192], sdirp[24], sdir[3], sgate[V_], sagg[48], svagg[48];
    __shared__ float red[8];

    const int row  = blockIdx.x;
    const int b    = row >> 9;
    const int i    = row & (N_-1);
    const int tid  = threadIdx.x;
    const int warp = tid>>5, lane = tid&31;
    const int half = lane>>4, hl = lane&15;

    if(tid<D_) sq[tid] = g_q[row*D_+tid];
    const float* cb = coords + (size_t)b*N_*3;
    for(int t=tid; t<N_*3; t+=256) scoord[t]=cb[t];
    const float biasRow = g_bias[row];
    __syncthreads();

    const float ci0 = scoord[i*3+0], ci1 = scoord[i*3+1], ci2 = scoord[i*3+2];

    // ---- pre-pass: all 512 dists (+ reciprocal) ----
    for(int j=tid; j<N_; j+=256){
        float dx = ci0 - scoord[j*3+0];
        float dy = ci1 - scoord[j*3+1];
        float dz = ci2 - scoord[j*3+2];
        float dist = sqrtf(fmaf(dx,dx,fmaf(dy,dy,dz*dz)));
        sdist[j] = dist;
        srd[j]   = __fdividef(1.0f, fmaxf(dist, 1e-6f));
    }
    __syncthreads();

    const float* kb   = g_k  + (size_t)b*N_*D_;
    const float* vvb  = g_vv + (size_t)b*N_*D_;
    const float* vecb = vector + (size_t)b*N_*3*V_;

    // per-lane constants: d = hl*8 + c, moment index p = hl+1 (hl<10)
    float qr[8];
    {
        const float4* p=(const float4*)sq;
        float4 a=p[hl*2], bb=p[hl*2+1];
        qr[0]=a.x;qr[1]=a.y;qr[2]=a.z;qr[3]=a.w; qr[4]=bb.x;qr[5]=bb.y;qr[6]=bb.z;qr[7]=bb.w;
    }
    const int pidx = hl+1;
    const bool u1 = (pidx&1), u2 = (pidx&2), u4 = (pidx&4), u8 = (pidx&8);
    const float qcl = (hl<10) ? g_qc[row*10+hl] : 0.0f;

    // ---- fused pass: 8 warps, 2 j's per warp-iter (16 lanes each, 8 d/lane)
    float Vc[8]={0,0,0,0,0,0,0,0};
    float Ml = 0.0f, sacc = 0.0f;

    #pragma unroll 2
    for(int base = warp*2; base < N_; base += 16){
        const int j = base + half;
        const float dist = sdist[j];

        const float4* krow = (const float4*)(kb + (size_t)j*D_);
        const float4* vrow = (const float4*)(vvb + (size_t)j*D_);
        float4 ka = krow[hl*2], kb4 = krow[hl*2+1];
        float4 va = vrow[hl*2], vb4 = vrow[hl*2+1];
        float kr[8] = {ka.x,ka.y,ka.z,ka.w,kb4.x,kb4.y,kb4.z,kb4.w};
        float vr[8] = {va.x,va.y,va.z,va.w,vb4.x,vb4.y,vb4.z,vb4.w};

        float d2 = dist*dist, d4 = d2*d2, d8 = d4*d4;
        float pw = (u1?dist:1.0f);
        pw *= (u2?d2:1.0f);
        pw *= (u4?d4:1.0f);
        pw *= (u8?d8:1.0f);

        float p = qcl*pw;
        #pragma unroll
        for(int c=0;c<8;c++) p = fmaf(qr[c], kr[c], p);

        p += __shfl_xor_sync(0xffffffffu, p, 8);
        p += __shfl_xor_sync(0xffffffffu, p, 4);
        p += __shfl_xor_sync(0xffffffffu, p, 2);
        p += __shfl_xor_sync(0xffffffffu, p, 1);

        float e = __expf(p + biasRow);
        if(hl==0) slog[j]=e;
        sacc += e;
        Ml = fmaf(e, pw, Ml);
        #pragma unroll
        for(int c=0;c<8;c++) Vc[c] = fmaf(e, vr[c], Vc[c]);
    }

    // merge halves within warp
    #pragma unroll
    for(int c=0;c<8;c++) Vc[c] += __shfl_xor_sync(0xffffffffu, Vc[c], 16);
    sacc += __shfl_xor_sync(0xffffffffu, sacc, 16);
    Ml   += __shfl_xor_sync(0xffffffffu, Ml, 16);
    if(half==0){
        #pragma unroll
        for(int c=0;c<8;c++) sVm[warp][hl*8+c]=Vc[c];
        if(hl<10) sMm[warp][hl]=Ml;
    }
    if(lane==0) sSum[warp]=sacc;
    __syncthreads();

    // merge 8 warps + normalize (slog stays raw; inv folded at consumers)
    const float inv = 1.0f/(((sSum[0]+sSum[1])+(sSum[2]+sSum[3]))+((sSum[4]+sSum[5])+(sSum[6]+sSum[7])));
    float Vd = 0.0f;
    if(tid<D_){
        Vd = (((sVm[0][tid]+sVm[1][tid])+(sVm[2][tid]+sVm[3][tid]))
            + ((sVm[4][tid]+sVm[5][tid])+(sVm[6][tid]+sVm[7][tid])))*inv;
    }
    if(tid<10) sMn[tid] = (((sMm[0][tid]+sMm[1][tid])+(sMm[2][tid]+sMm[3][tid]))
                          +((sMm[4][tid]+sMm[5][tid])+(sMm[6][tid]+sMm[7][tid])))*inv;
    __syncthreads();

    // ---- H reconstruction from moments (tid<128) ----
    if(tid<D_){
        float C[11];
        gelu_coeffs(w_d1[tid], b_d1[tid], C);
        float Hd = C[0];
        #pragma unroll
        for(int p=1;p<11;p++) Hd = fmaf(C[p], sMn[p-1], Hd);
        sH[tid]=Hd;
    }

    // ---- vector aggregation (192 thr) + direction aggregation (24 thr) ----
    if(tid < 192){
        const int g4 = tid/48, t48 = tid - g4*48;
        const int j0 = g4*128;
        float a0=0,a1=0;
        #pragma unroll 4
        for(int j=j0;j<j0+128;j+=2){
            a0 = fmaf(slog[j],   vecb[(size_t)j*48+t48],     a0);
            a1 = fmaf(slog[j+1], vecb[(size_t)(j+1)*48+t48], a1);
        }
        svagg4[tid]=a0+a1;
    } else if(tid < 216){
        const int idx = tid-192, c = idx>>3, g = idx&7;
        const float cic = scoord[i*3+c];
        float acc=0.0f;
        for(int j=g;j<N_;j+=8){
            acc = fmaf(slog[j]*srd[j], cic - scoord[j*3+c], acc);
        }
        sdirp[idx]=acc;
    }
    __syncthreads();
    if(tid<48) svagg[tid]=(((svagg4[tid]+svagg4[tid+48])+(svagg4[tid+96]+svagg4[tid+144])))*inv;
    if(tid<3){
        float a=0;
        #pragma unroll
        for(int g=0;g<8;g++) a+=sdirp[tid*8+g];
        sdir[tid]=a*inv;
    }

    // ---- upd = attn@v + H@w_d2 + b_d2  (split-K over 256 threads) ----
    {
        const int od = tid & 127, hf = tid >> 7;
        const int e0 = hf*64;
        float u0=0,u1=0;
        #pragma unroll 8
        for(int e=e0;e<e0+64;e+=2){
            u0 = fmaf(sH[e+0], w_d2[(e+0)*D_+od], u0);
            u1 = fmaf(sH[e+1], w_d2[(e+1)*D_+od], u1);
        }
        spart[tid]=u0+u1;
    }
    __syncthreads();
    if(tid<D_) sbuf[tid] = Vd + b_d2[tid] + spart[tid]+spart[tid+128];
    __syncthreads();

    // ---- scalar1 = scalar + upd@w_o + b_o  (split-K) ----
    {
        const int od = tid & 127, hf = tid >> 7;
        const int e0 = hf*64;
        float u0=0,u1=0;
        #pragma unroll 8
        for(int e=e0;e<e0+64;e+=2){
            u0 = fmaf(sbuf[e+0], w_o[(e+0)*D_+od], u0);
            u1 = fmaf(sbuf[e+1], w_o[(e+1)*D_+od], u1);
        }
        spart[tid]=u0+u1;
    }
    __syncthreads();
    float s1 = 0.0f;
    if(tid<D_){
        s1 = scalar[row*D_+tid] + b_o[tid] + spart[tid]+spart[tid+128];
        sscal[tid]=s1;
    }

    // ---- LN (256-thread reduction, only tid<128 contribute) ----
    float xc = (tid<D_)? s1 : 0.0f;
    float m  = blockSum256(xc, red)*(1.0f/D_);
    float dvc= (tid<D_)? (s1-m) : 0.0f;
    float var= blockSum256(dvc*dvc, red)*(1.0f/D_);
    if(tid<D_){
        float hn = (s1-m)*rsqrtf(var+1e-5f)*g_s[tid] + be_s[tid];
        shn[tid]=hn;
    }
    __syncthreads();

    // ---- FFN layer 1: one output per thread (256 outputs) ----
    {
        const int m2 = tid;
        float u0=0,u1=0,u2=0,u3=0;
        #pragma unroll 4
        for(int e=0;e<D_;e+=4){
            u0 = fmaf(shn[e+0], w_f1[(e+0)*2*D_+m2], u0);
            u1 = fmaf(shn[e+1], w_f1[(e+1)*2*D_+m2], u1);
            u2 = fmaf(shn[e+2], w_f1[(e+2)*2*D_+m2], u2);
            u3 = fmaf(shn[e+3], w_f1[(e+3)*2*D_+m2], u3);
        }
        sf[m2]=geluf(b_f1[m2] + (u0+u1)+(u2+u3));
    }
    __syncthreads();

    // ---- FFN layer 2 (split-K over 256 threads, K=256) ----
    {
        const int od = tid & 127, hf = tid >> 7;
        const int e0 = hf*128;
        float u0=0,u1=0;
        #pragma unroll 8
        for(int e=e0;e<e0+128;e+=2){
            u0 = fmaf(sf[e+0], w_f2[(e+0)*D_+od], u0);
            u1 = fmaf(sf[e+1], w_f2[(e+1)*D_+od], u1);
        }
        spart[tid]=u0+u1;
    }
    __syncthreads();
    if(tid<D_){
        float s2 = sscal[tid] + b_f2[tid] + spart[tid]+spart[tid+128];
        out_scalar[row*D_+tid] = s2;
        sscal[tid] = s2;
    }
    __syncthreads();

    // ---- gate ----
    if(tid<V_){
        float u0=0,u1=0,u2=0,u3=0;
        #pragma unroll 4
        for(int d2=0;d2<D_;d2+=4){
            u0 = fmaf(sscal[d2+0], w_g[(d2+0)*V_+tid], u0);
            u1 = fmaf(sscal[d2+1], w_g[(d2+1)*V_+tid], u1);
            u2 = fmaf(sscal[d2+2], w_g[(d2+2)*V_+tid], u2);
            u3 = fmaf(sscal[d2+3], w_g[(d2+3)*V_+tid], u3);
        }
        float a = b_g[tid] + (u0+u1)+(u2+u3);
        sgate[tid] = 1.0f/(1.0f+__expf(-a));
    }
    __syncthreads();

    // ---- agg, LN over V, proj, vector residual ----
    if(tid<48){
        int c = tid>>4, vv = tid&15;
        sagg[tid] = svagg[tid] + sdir[c]*sgate[vv];
    }
    __syncthreads();
    if(tid<48){
        int c = tid>>4, vv = tid&15;
        float m2=0.0f;
        #pragma unroll
        for(int u=0;u<V_;u++) m2 += sagg[c*V_+u];
        m2 *= (1.0f/V_);
        float var2=0.0f;
        #pragma unroll
        for(int u=0;u<V_;u++){ float d3=sagg[c*V_+u]-m2; var2 += d3*d3; }
        var2 *= (1.0f/V_);
        float invr = rsqrtf(var2+1e-5f);
        float acc = b_vo[vv];
        #pragma unroll
        for(int u=0;u<V_;u++){
            float lnu = (sagg[c*V_+u]-m2)*invr*g_v_[u] + be_v[u];
            acc = fmaf(lnu, w_vo[u*V_+vv], acc);
        }
        out_vector[row*3*V_+tid] = vecb[(size_t)i*3*V_+tid] + acc;
    }
}

extern "C" void kernel_launch(void* const* d_in, const int* in_sizes, int n_in,
                              void* d_out, int out_size)
{
    const float* scalar = (const float*)d_in[0];
    const float* vector = (const float*)d_in[1];
    const float* coords = (const float*)d_in[2];
    const float* w_q  = (const float*)d_in[3];  const float* b_q  = (const float*)d_in[4];
    const float* w_k  = (const float*)d_in[5];  const float* b_k  = (const float*)d_in[6];
    const float* w_v  = (const float*)d_in[7];  const float* b_v  = (const float*)d_in[8];
    const float* w_d1 = (const float*)d_in[9];  const float* b_d1 = (const float*)d_in[10];
    const float* w_d2 = (const float*)d_in[11]; const float* b_d2 = (const float*)d_in[12];
    const float* w_g  = (const float*)d_in[13]; const float* b_g  = (const float*)d_in[14];
    const float* w_o  = (const float*)d_in[15]; const float* b_o  = (const float*)d_in[16];
    const float* w_f1 = (const float*)d_in[17]; const float* b_f1 = (const float*)d_in[18];
    const float* w_f2 = (const float*)d_in[19]; const float* b_f2 = (const float*)d_in[20];
    const float* w_vo = (const float*)d_in[21]; const float* b_vo = (const float*)d_in[22];
    const float* g_s  = (const float*)d_in[23]; const float* be_s = (const float*)d_in[24];
    const float* g_v  = (const float*)d_in[25]; const float* be_v = (const float*)d_in[26];

    float* out = (float*)d_out;
    float* out_scalar = out;
    float* out_vector = out + (size_t)ROWS*D_;

    prep_kernel<<<ROWS,128>>>(scalar, w_q,b_q, w_k,b_k, w_v,b_v,
                              w_d1,b_d1, w_d2,b_d2, g_s,be_s);
    main_kernel<<<ROWS,256>>>(scalar, vector, coords,
                              w_d1,b_d1, w_d2,b_d2, w_g,b_g, w_o,b_o,
                              w_f1,b_f1, w_f2,b_f2, w_vo,b_vo,
                              g_s,be_s, g_v,be_v,
                              out_scalar, out_vector);
}

// round 7
// speedup vs baseline: 1.6384x; 1.5471x over previous
#include <cuda_runtime.h>
#include <math.h>

#define B_ 2
#define N_ 512
#define D_ 128
#define V_ 16
#define ROWS (B_*N_)

// scratch (allocation-free rule: __device__ globals)
__device__ float g_q  [ROWS*D_];     // q * invS
__device__ float g_k  [ROWS*D_];     // unused by main now, kept small cost
__device__ float g_kT [B_*D_*N_];    // k transposed: [b][d][j]
__device__ float g_vv [ROWS*D_];
__device__ float g_Wc [D_*12];       // Wc[d][p] p=0..10, col 11 = b_d2[d]

__device__ __forceinline__ float geluf(float x){
    return 0.5f*x*(1.0f+erff(x*0.70710678118654752f));
}
// polynomial coefficients of gelu_fast(w*t+b) in powers of t (degree 10)
__device__ __forceinline__ void gelu_coeffs(float w, float b, float C[11]){
    const float K  = 0.3989422804014327f;
    const float c2 = K;
    const float c4 = K*-0.16666666666667f;
    const float c6 = K*0.025f;
    const float c8 = K*-2.9761904761905e-3f;
    const float c10= K*2.8935185185185e-4f;
    float wp[11], bp[11];
    wp[0]=1.f; bp[0]=1.f;
    #pragma unroll
    for(int t=1;t<11;t++){ wp[t]=wp[t-1]*w; bp[t]=bp[t-1]*b; }
    #pragma unroll
    for(int p=0;p<11;p++) C[p]=0.f;
    C[0] += 0.5f*b; C[1] += 0.5f*w;
    const float B2[3]={1,2,1};
    const float B4[5]={1,4,6,4,1};
    const float B6[7]={1,6,15,20,15,6,1};
    const float B8[9]={1,8,28,56,70,56,28,8,1};
    const float B10[11]={1,10,45,120,210,252,210,120,45,10,1};
    #pragma unroll
    for(int p=0;p<=2;p++)  C[p] += c2 *B2[p] *wp[p]*bp[2-p];
    #pragma unroll
    for(int p=0;p<=4;p++)  C[p] += c4 *B4[p] *wp[p]*bp[4-p];
    #pragma unroll
    for(int p=0;p<=6;p++)  C[p] += c6 *B6[p] *wp[p]*bp[6-p];
    #pragma unroll
    for(int p=0;p<=8;p++)  C[p] += c8 *B8[p] *wp[p]*bp[8-p];
    #pragma unroll
    for(int p=0;p<=10;p++) C[p] += c10*B10[p]*wp[p]*bp[10-p];
}
__device__ __forceinline__ float warpSum(float v){
    #pragma unroll
    for(int o=16;o;o>>=1) v += __shfl_down_sync(0xffffffffu, v, o);
    return v;
}
// 256-thread block reduction (main kernel)
__device__ __forceinline__ float blockSum256(float v, float* red){
    int w = threadIdx.x>>5, l = threadIdx.x&31;
    v = warpSum(v);
    if(l==0) red[w]=v;
    __syncthreads();
    if(threadIdx.x==0){
        float s = 0.f;
        #pragma unroll
        for(int k=0;k<8;k++) s += red[k];
        red[0]=s;
    }
    __syncthreads();
    float r = red[0];
    __syncthreads();
    return r;
}

// ---------------- Kernel 0: Wc = W_d2^T C^T  (one block, once) -------------
__global__ void __launch_bounds__(128) setup_kernel(
    const float* __restrict__ w_d1, const float* __restrict__ b_d1,
    const float* __restrict__ w_d2, const float* __restrict__ b_d2)
{
    __shared__ float sC[11][D_];
    const int t = threadIdx.x;
    {
        float C[11];
        gelu_coeffs(w_d1[t], b_d1[t], C);
        #pragma unroll
        for(int p=0;p<11;p++) sC[p][t]=C[p];
    }
    __syncthreads();
    float acc[11];
    #pragma unroll
    for(int p=0;p<11;p++) acc[p]=0.f;
    for(int e=0;e<D_;e++){
        float w = w_d2[e*D_+t];
        #pragma unroll
        for(int p=0;p<11;p++) acc[p] = fmaf(sC[p][e], w, acc[p]);
    }
    #pragma unroll
    for(int p=0;p<11;p++) g_Wc[t*12+p]=acc[p];
    g_Wc[t*12+11]=b_d2[t];
}

// ---------------- Kernel A: LN + q/k/v, 4 rows per block -------------------
__global__ void __launch_bounds__(128) prep_kernel(
    const float* __restrict__ scalar,
    const float* __restrict__ w_q, const float* __restrict__ b_q,
    const float* __restrict__ w_k, const float* __restrict__ b_k,
    const float* __restrict__ w_v, const float* __restrict__ b_v,
    const float* __restrict__ g_s, const float* __restrict__ be_s)
{
    __shared__ float ssn[4][D_];
    const int row0 = blockIdx.x*4;
    const int d = threadIdx.x;
    const int warp = d>>5, lane = d&31;
    const float invS = 0.0883883476483184f; // 1/sqrt(128)

    // LN: warp r handles row row0+r
    {
        const float* xr = scalar + (size_t)(row0+warp)*D_;
        float v0=xr[lane], v1=xr[lane+32], v2=xr[lane+64], v3=xr[lane+96];
        float s = (v0+v1)+(v2+v3);
        s = warpSum(s); s = __shfl_sync(0xffffffffu, s, 0);
        float m = s*(1.0f/D_);
        float d0=v0-m, d1=v1-m, d2=v2-m, d3=v3-m;
        float vs = (d0*d0+d1*d1)+(d2*d2+d3*d3);
        vs = warpSum(vs); vs = __shfl_sync(0xffffffffu, vs, 0);
        float rstd = rsqrtf(vs*(1.0f/D_)+1e-5f);
        ssn[warp][lane   ] = d0*rstd*g_s[lane   ]+be_s[lane   ];
        ssn[warp][lane+32] = d1*rstd*g_s[lane+32]+be_s[lane+32];
        ssn[warp][lane+64] = d2*rstd*g_s[lane+64]+be_s[lane+64];
        ssn[warp][lane+96] = d3*rstd*g_s[lane+96]+be_s[lane+96];
    }
    __syncthreads();

    // matvec: thread = output d, 4 rows amortize weight loads
    float qa[4]={0,0,0,0}, ka[4]={0,0,0,0}, va[4]={0,0,0,0};
    #pragma unroll 4
    for(int e=0;e<D_;e++){
        float wq=w_q[e*D_+d], wk=w_k[e*D_+d], wv=w_v[e*D_+d];
        float s0=ssn[0][e], s1=ssn[1][e], s2=ssn[2][e], s3=ssn[3][e];
        qa[0]=fmaf(s0,wq,qa[0]); qa[1]=fmaf(s1,wq,qa[1]); qa[2]=fmaf(s2,wq,qa[2]); qa[3]=fmaf(s3,wq,qa[3]);
        ka[0]=fmaf(s0,wk,ka[0]); ka[1]=fmaf(s1,wk,ka[1]); ka[2]=fmaf(s2,wk,ka[2]); ka[3]=fmaf(s3,wk,ka[3]);
        va[0]=fmaf(s0,wv,va[0]); va[1]=fmaf(s1,wv,va[1]); va[2]=fmaf(s2,wv,va[2]); va[3]=fmaf(s3,wv,va[3]);
    }
    const float bq=b_q[d], bk=b_k[d], bv=b_v[d];
    #pragma unroll
    for(int r=0;r<4;r++){
        const int row = row0+r;
        const int b = row>>9, il = row&(N_-1);
        float q = qa[r]+bq;
        float k = ka[r]+bk;
        g_q [(size_t)row*D_+d]=q*invS;
        g_k [(size_t)row*D_+d]=k;
        g_kT[((size_t)(b*D_+d))*N_+il]=k;
        g_vv[(size_t)row*D_+d]=va[r]+bv;
    }
}

// ---------------- Kernel B: fused attention + epilogues, 256 thr/row --------
__global__ void __launch_bounds__(256, 4) main_kernel(
    const float* __restrict__ scalar, const float* __restrict__ vector,
    const float* __restrict__ coords,
    const float* __restrict__ w_d1, const float* __restrict__ b_d1,
    const float* __restrict__ w_d2, const float* __restrict__ b_d2,
    const float* __restrict__ w_g,  const float* __restrict__ b_g,
    const float* __restrict__ w_o,  const float* __restrict__ b_o,
    const float* __restrict__ w_f1, const float* __restrict__ b_f1,
    const float* __restrict__ w_f2, const float* __restrict__ b_f2,
    const float* __restrict__ w_vo, const float* __restrict__ b_vo,
    const float* __restrict__ g_s,  const float* __restrict__ be_s,
    const float* __restrict__ g_v_, const float* __restrict__ be_v,
    float* __restrict__ out_scalar, float* __restrict__ out_vector)
{
    __shared__ float sq[D_];
    __shared__ float scoord[N_*3];
    __shared__ float sdist[N_], srd[N_], slog[N_];
    __shared__ float sQC[12];
    __shared__ float sMm[8][11], sMtot[11], sMn[10];
    __shared__ float sH[D_], sbuf[D_], sscal[D_], shn[D_], sf[2*D_];
    __shared__ float spart[256];
    __shared__ float svagg4[192], sdirp[24], sdir[3], sgate[V_], sagg[48], svagg[48];
    __shared__ float red[8];

    const int row  = blockIdx.x;
    const int b    = row >> 9;
    const int i    = row & (N_-1);
    const int tid  = threadIdx.x;
    const int warp = tid>>5, lane = tid&31;

    if(tid<D_) sq[tid] = g_q[(size_t)row*D_+tid];
    const float* cb = coords + (size_t)b*N_*3;
    for(int t=tid; t<N_*3; t+=256) scoord[t]=cb[t];
    __syncthreads();

    const float ci0 = scoord[i*3+0], ci1 = scoord[i*3+1], ci2 = scoord[i*3+2];

    // ---- pre-pass: dists + reciprocals ----
    for(int j=tid; j<N_; j+=256){
        float dx = ci0 - scoord[j*3+0];
        float dy = ci1 - scoord[j*3+1];
        float dz = ci2 - scoord[j*3+2];
        float dist = sqrtf(fmaf(dx,dx,fmaf(dy,dy,dz*dz)));
        sdist[j] = dist;
        srd[j]   = __fdividef(1.0f, fmaxf(dist, 1e-6f));
    }
    // ---- qc reductions: 12 dots sq . Wc[:,m] ----
    for(int m=warp; m<12; m+=8){
        float a=0.f;
        #pragma unroll
        for(int c=0;c<4;c++){
            int d = lane + 32*c;
            a = fmaf(sq[d], g_Wc[d*12+m], a);
        }
        a = warpSum(a);
        if(lane==0) sQC[m]=a;
    }
    __syncthreads();

    const float biasv = sQC[0] + sQC[11];
    float qcr[10];
    #pragma unroll
    for(int p=0;p<10;p++) qcr[p]=sQC[p+1];

    const float* kTb  = g_kT + (size_t)b*D_*N_;
    const float* vvb  = g_vv + (size_t)b*N_*D_;
    const float* vecb = vector + (size_t)b*N_*3*V_;

    // ---- pass 1: lane = j. Each warp: 32 j's, two chunks ----
    float M[11];
    #pragma unroll
    for(int m=0;m<11;m++) M[m]=0.f;

    #pragma unroll
    for(int chunk=0; chunk<2; chunk++){
        const int j = warp*32 + lane + chunk*256;
        const float* kcol = kTb + j;
        float p0=0.f,p1=0.f,p2=0.f,p3=0.f;
        #pragma unroll 4
        for(int d=0; d<D_; d+=4){
            p0 = fmaf(sq[d+0], kcol[(size_t)(d+0)*N_], p0);
            p1 = fmaf(sq[d+1], kcol[(size_t)(d+1)*N_], p1);
            p2 = fmaf(sq[d+2], kcol[(size_t)(d+2)*N_], p2);
            p3 = fmaf(sq[d+3], kcol[(size_t)(d+3)*N_], p3);
        }
        const float dist = sdist[j];
        // Horner: sum_{p=1..10} qc[p] dist^p
        float pol = qcr[9];
        #pragma unroll
        for(int p=8;p>=0;p--) pol = fmaf(pol, dist, qcr[p]);
        pol *= dist;
        float logit = ((p0+p1)+(p2+p3)) + pol + biasv;
        float e = __expf(logit);
        slog[j]=e;
        M[10] += e;
        float t = dist;
        #pragma unroll
        for(int p=0;p<10;p++){ M[p] = fmaf(e, t, M[p]); t *= dist; }
    }
    // interleaved warp reduce of 11 moments
    #pragma unroll
    for(int o=16;o;o>>=1){
        #pragma unroll
        for(int m=0;m<11;m++) M[m] += __shfl_down_sync(0xffffffffu, M[m], o);
    }
    if(lane==0){
        #pragma unroll
        for(int m=0;m<11;m++) sMm[warp][m]=M[m];
    }
    __syncthreads();
    if(tid<11){
        float s = ((sMm[0][tid]+sMm[1][tid])+(sMm[2][tid]+sMm[3][tid]))
                + ((sMm[4][tid]+sMm[5][tid])+(sMm[6][tid]+sMm[7][tid]));
        sMtot[tid]=s;
    }
    __syncthreads();
    const float inv = 1.0f/sMtot[10];
    if(tid<10) sMn[tid] = sMtot[tid]*inv;

    // ---- pass 2: V accumulation, thread = (d, j-half) ----
    {
        const int d = tid & 127, jh = tid >> 7;
        const int j0 = jh*256;
        const float* vcol = vvb + d;
        float a0=0.f,a1=0.f,a2=0.f,a3=0.f;
        #pragma unroll 8
        for(int jj=0; jj<256; jj+=4){
            a0 = fmaf(slog[j0+jj+0], vcol[(size_t)(j0+jj+0)*D_], a0);
            a1 = fmaf(slog[j0+jj+1], vcol[(size_t)(j0+jj+1)*D_], a1);
            a2 = fmaf(slog[j0+jj+2], vcol[(size_t)(j0+jj+2)*D_], a2);
            a3 = fmaf(slog[j0+jj+3], vcol[(size_t)(j0+jj+3)*D_], a3);
        }
        spart[tid]=(a0+a1)+(a2+a3);
    }
    __syncthreads();
    float Vd = 0.0f;
    if(tid<D_) Vd = (spart[tid]+spart[tid+128])*inv;

    // ---- H reconstruction from moments (tid<128) ----
    if(tid<D_){
        float C[11];
        gelu_coeffs(w_d1[tid], b_d1[tid], C);
        float Hd = C[0];
        #pragma unroll
        for(int p=1;p<11;p++) Hd = fmaf(C[p], sMn[p-1], Hd);
        sH[tid]=Hd;
    }

    // ---- vector aggregation (192 thr) + direction aggregation (24 thr) ----
    if(tid < 192){
        const int g4 = tid/48, t48 = tid - g4*48;
        const int j0 = g4*128;
        float a0=0,a1=0;
        #pragma unroll 4
        for(int j=j0;j<j0+128;j+=2){
            a0 = fmaf(slog[j],   vecb[(size_t)j*48+t48],     a0);
            a1 = fmaf(slog[j+1], vecb[(size_t)(j+1)*48+t48], a1);
        }
        svagg4[tid]=a0+a1;
    } else if(tid < 216){
        const int idx = tid-192, c = idx>>3, g = idx&7;
        const float cic = scoord[i*3+c];
        float acc=0.0f;
        for(int j=g;j<N_;j+=8){
            acc = fmaf(slog[j]*srd[j], cic - scoord[j*3+c], acc);
        }
        sdirp[idx]=acc;
    }
    __syncthreads();
    if(tid<48) svagg[tid]=(((svagg4[tid]+svagg4[tid+48])+(svagg4[tid+96]+svagg4[tid+144])))*inv;
    if(tid<3){
        float a=0;
        #pragma unroll
        for(int g=0;g<8;g++) a+=sdirp[tid*8+g];
        sdir[tid]=a*inv;
    }
    __syncthreads();

    // ---- upd = attn@v + H@w_d2 + b_d2  (split-K over 256 threads) ----
    {
        const int od = tid & 127, hf = tid >> 7;
        const int e0 = hf*64;
        float u0=0,u1=0;
        #pragma unroll 8
        for(int e=e0;e<e0+64;e+=2){
            u0 = fmaf(sH[e+0], w_d2[(e+0)*D_+od], u0);
            u1 = fmaf(sH[e+1], w_d2[(e+1)*D_+od], u1);
        }
        spart[tid]=u0+u1;
    }
    __syncthreads();
    if(tid<D_) sbuf[tid] = Vd + b_d2[tid] + spart[tid]+spart[tid+128];
    __syncthreads();

    // ---- scalar1 = scalar + upd@w_o + b_o  (split-K) ----
    {
        const int od = tid & 127, hf = tid >> 7;
        const int e0 = hf*64;
        float u0=0,u1=0;
        #pragma unroll 8
        for(int e=e0;e<e0+64;e+=2){
            u0 = fmaf(sbuf[e+0], w_o[(e+0)*D_+od], u0);
            u1 = fmaf(sbuf[e+1], w_o[(e+1)*D_+od], u1);
        }
        spart[tid]=u0+u1;
    }
    __syncthreads();
    float s1 = 0.0f;
    if(tid<D_){
        s1 = scalar[(size_t)row*D_+tid] + b_o[tid] + spart[tid]+spart[tid+128];
        sscal[tid]=s1;
    }

    // ---- LN ----
    float xc = (tid<D_)? s1 : 0.0f;
    float m  = blockSum256(xc, red)*(1.0f/D_);
    float dvc= (tid<D_)? (s1-m) : 0.0f;
    float var= blockSum256(dvc*dvc, red)*(1.0f/D_);
    if(tid<D_){
        float hn = (s1-m)*rsqrtf(var+1e-5f)*g_s[tid] + be_s[tid];
        shn[tid]=hn;
    }
    __syncthreads();

    // ---- FFN layer 1: one output per thread ----
    {
        const int m2 = tid;
        float u0=0,u1=0,u2=0,u3=0;
        #pragma unroll 4
        for(int e=0;e<D_;e+=4){
            u0 = fmaf(shn[e+0], w_f1[(e+0)*2*D_+m2], u0);
            u1 = fmaf(shn[e+1], w_f1[(e+1)*2*D_+m2], u1);
            u2 = fmaf(shn[e+2], w_f1[(e+2)*2*D_+m2], u2);
            u3 = fmaf(shn[e+3], w_f1[(e+3)*2*D_+m2], u3);
        }
        sf[m2]=geluf(b_f1[m2] + (u0+u1)+(u2+u3));
    }
    __syncthreads();

    // ---- FFN layer 2 (split-K, K=256) ----
    {
        const int od = tid & 127, hf = tid >> 7;
        const int e0 = hf*128;
        float u0=0,u1=0;
        #pragma unroll 8
        for(int e=e0;e<e0+128;e+=2){
            u0 = fmaf(sf[e+0], w_f2[(e+0)*D_+od], u0);
            u1 = fmaf(sf[e+1], w_f2[(e+1)*D_+od], u1);
        }
        spart[tid]=u0+u1;
    }
    __syncthreads();
    if(tid<D_){
        float s2 = sscal[tid] + b_f2[tid] + spart[tid]+spart[tid+128];
        out_scalar[(size_t)row*D_+tid] = s2;
        sscal[tid] = s2;
    }
    __syncthreads();

    // ---- gate ----
    if(tid<V_){
        float u0=0,u1=0,u2=0,u3=0;
        #pragma unroll 4
        for(int d2=0;d2<D_;d2+=4){
            u0 = fmaf(sscal[d2+0], w_g[(d2+0)*V_+tid], u0);
            u1 = fmaf(sscal[d2+1], w_g[(d2+1)*V_+tid], u1);
            u2 = fmaf(sscal[d2+2], w_g[(d2+2)*V_+tid], u2);
            u3 = fmaf(sscal[d2+3], w_g[(d2+3)*V_+tid], u3);
        }
        float a = b_g[tid] + (u0+u1)+(u2+u3);
        sgate[tid] = 1.0f/(1.0f+__expf(-a));
    }
    __syncthreads();

    // ---- agg, LN over V, proj, vector residual ----
    if(tid<48){
        int c = tid>>4, vv = tid&15;
        sagg[tid] = svagg[tid] + sdir[c]*sgate[vv];
    }
    __syncthreads();
    if(tid<48){
        int c = tid>>4, vv = tid&15;
        float m2=0.0f;
        #pragma unroll
        for(int u=0;u<V_;u++) m2 += sagg[c*V_+u];
        m2 *= (1.0f/V_);
        float var2=0.0f;
        #pragma unroll
        for(int u=0;u<V_;u++){ float d3=sagg[c*V_+u]-m2; var2 += d3*d3; }
        var2 *= (1.0f/V_);
        float invr = rsqrtf(var2+1e-5f);
        float acc = b_vo[vv];
        #pragma unroll
        for(int u=0;u<V_;u++){
            float lnu = (sagg[c*V_+u]-m2)*invr*g_v_[u] + be_v[u];
            acc = fmaf(lnu, w_vo[u*V_+vv], acc);
        }
        out_vector[(size_t)row*3*V_+tid] = vecb[(size_t)i*3*V_+tid] + acc;
    }
}

extern "C" void kernel_launch(void* const* d_in, const int* in_sizes, int n_in,
                              void* d_out, int out_size)
{
    const float* scalar = (const float*)d_in[0];
    const float* vector = (const float*)d_in[1];
    const float* coords = (const float*)d_in[2];
    const float* w_q  = (const float*)d_in[3];  const float* b_q  = (const float*)d_in[4];
    const float* w_k  = (const float*)d_in[5];  const float* b_k  = (const float*)d_in[6];
    const float* w_v  = (const float*)d_in[7];  const float* b_v  = (const float*)d_in[8];
    const float* w_d1 = (const float*)d_in[9];  const float* b_d1 = (const float*)d_in[10];
    const float* w_d2 = (const float*)d_in[11]; const float* b_d2 = (const float*)d_in[12];
    const float* w_g  = (const float*)d_in[13]; const float* b_g  = (const float*)d_in[14];
    const float* w_o  = (const float*)d_in[15]; const float* b_o  = (const float*)d_in[16];
    const float* w_f1 = (const float*)d_in[17]; const float* b_f1 = (const float*)d_in[18];
    const float* w_f2 = (const float*)d_in[19]; const float* b_f2 = (const float*)d_in[20];
    const float* w_vo = (const float*)d_in[21]; const float* b_vo = (const float*)d_in[22];
    const float* g_s  = (const float*)d_in[23]; const float* be_s = (const float*)d_in[24];
    const float* g_v  = (const float*)d_in[25]; const float* be_v = (const float*)d_in[26];

    float* out = (float*)d_out;
    float* out_scalar = out;
    float* out_vector = out + (size_t)ROWS*D_;

    setup_kernel<<<1,128>>>(w_d1,b_d1,w_d2,b_d2);
    prep_kernel<<<ROWS/4,128>>>(scalar, w_q,b_q, w_k,b_k, w_v,b_v, g_s,be_s);
    main_kernel<<<ROWS,256>>>(scalar, vector, coords,
                              w_d1,b_d1, w_d2,b_d2, w_g,b_g, w_o,b_o,
                              w_f1,b_f1, w_f2,b_f2, w_vo,b_vo,
                              g_s,be_s, g_v,be_v,
                              out_scalar, out_vector);
}

// round 8
// speedup vs baseline: 1.9482x; 1.1891x over previous
#include <cuda_runtime.h>
#include <cuda_fp16.h>
#include <math.h>

#define B_ 2
#define N_ 512
#define D_ 128
#define V_ 16
#define ROWS (B_*N_)

// scratch (allocation-free rule: __device__ globals)
__device__ float   g_q  [ROWS*D_];       // q * invS
__device__ __half2 g_kh [B_*(D_/2)*N_];  // [b][u][j] = (k[2u][j], k[2u+1][j])
__device__ __half2 g_vh [B_*N_*(D_/2)];  // [b][j][u] = (v[2u], v[2u+1])
__device__ float   g_Wc [D_*12];         // Wc[d][p] p=0..10, col 11 = b_d2[d]

__device__ __forceinline__ float geluf(float x){
    return 0.5f*x*(1.0f+erff(x*0.70710678118654752f));
}
// polynomial coefficients of gelu_fast(w*t+b) in powers of t (degree 10)
__device__ __forceinline__ void gelu_coeffs(float w, float b, float C[11]){
    const float K  = 0.3989422804014327f;
    const float c2 = K;
    const float c4 = K*-0.16666666666667f;
    const float c6 = K*0.025f;
    const float c8 = K*-2.9761904761905e-3f;
    const float c10= K*2.8935185185185e-4f;
    float wp[11], bp[11];
    wp[0]=1.f; bp[0]=1.f;
    #pragma unroll
    for(int t=1;t<11;t++){ wp[t]=wp[t-1]*w; bp[t]=bp[t-1]*b; }
    #pragma unroll
    for(int p=0;p<11;p++) C[p]=0.f;
    C[0] += 0.5f*b; C[1] += 0.5f*w;
    const float B2[3]={1,2,1};
    const float B4[5]={1,4,6,4,1};
    const float B6[7]={1,6,15,20,15,6,1};
    const float B8[9]={1,8,28,56,70,56,28,8,1};
    const float B10[11]={1,10,45,120,210,252,210,120,45,10,1};
    #pragma unroll
    for(int p=0;p<=2;p++)  C[p] += c2 *B2[p] *wp[p]*bp[2-p];
    #pragma unroll
    for(int p=0;p<=4;p++)  C[p] += c4 *B4[p] *wp[p]*bp[4-p];
    #pragma unroll
    for(int p=0;p<=6;p++)  C[p] += c6 *B6[p] *wp[p]*bp[6-p];
    #pragma unroll
    for(int p=0;p<=8;p++)  C[p] += c8 *B8[p] *wp[p]*bp[8-p];
    #pragma unroll
    for(int p=0;p<=10;p++) C[p] += c10*B10[p]*wp[p]*bp[10-p];
}
__device__ __forceinline__ float warpSum(float v){
    #pragma unroll
    for(int o=16;o;o>>=1) v += __shfl_down_sync(0xffffffffu, v, o);
    return v;
}
// 256-thread block reduction (main kernel)
__device__ __forceinline__ float blockSum256(float v, float* red){
    int w = threadIdx.x>>5, l = threadIdx.x&31;
    v = warpSum(v);
    if(l==0) red[w]=v;
    __syncthreads();
    if(threadIdx.x==0){
        float s = 0.f;
        #pragma unroll
        for(int k=0;k<8;k++) s += red[k];
        red[0]=s;
    }
    __syncthreads();
    float r = red[0];
    __syncthreads();
    return r;
}

// ---------- Kernel A: LN + q/k/v (4 rows/blk); last block does Wc setup -----
__global__ void __launch_bounds__(128) prep_kernel(
    const float* __restrict__ scalar,
    const float* __restrict__ w_q, const float* __restrict__ b_q,
    const float* __restrict__ w_k, const float* __restrict__ b_k,
    const float* __restrict__ w_v, const float* __restrict__ b_v,
    const float* __restrict__ w_d1, const float* __restrict__ b_d1,
    const float* __restrict__ w_d2, const float* __restrict__ b_d2,
    const float* __restrict__ g_s, const float* __restrict__ be_s)
{
    __shared__ float ssn[4][D_];
    __shared__ float sk4[4][D_], sv4[4][D_];
    __shared__ float sC[11][D_];
    const int d = threadIdx.x;

    if(blockIdx.x == ROWS/4){
        // ---- setup: Wc = W_d2^T C^T ----
        {
            float C[11];
            gelu_coeffs(w_d1[d], b_d1[d], C);
            #pragma unroll
            for(int p=0;p<11;p++) sC[p][d]=C[p];
        }
        __syncthreads();
        float acc[11];
        #pragma unroll
        for(int p=0;p<11;p++) acc[p]=0.f;
        #pragma unroll 4
        for(int e=0;e<D_;e++){
            float w = w_d2[e*D_+d];
            #pragma unroll
            for(int p=0;p<11;p++) acc[p] = fmaf(sC[p][e], w, acc[p]);
        }
        #pragma unroll
        for(int p=0;p<11;p++) g_Wc[d*12+p]=acc[p];
        g_Wc[d*12+11]=b_d2[d];
        return;
    }

    const int row0 = blockIdx.x*4;
    const int warp = d>>5, lane = d&31;
    const float invS = 0.0883883476483184f; // 1/sqrt(128)

    // LN: warp r handles row row0+r
    {
        const float* xr = scalar + (size_t)(row0+warp)*D_;
        float v0=xr[lane], v1=xr[lane+32], v2=xr[lane+64], v3=xr[lane+96];
        float s = (v0+v1)+(v2+v3);
        s = warpSum(s); s = __shfl_sync(0xffffffffu, s, 0);
        float m = s*(1.0f/D_);
        float d0=v0-m, d1=v1-m, d2=v2-m, d3=v3-m;
        float vs = (d0*d0+d1*d1)+(d2*d2+d3*d3);
        vs = warpSum(vs); vs = __shfl_sync(0xffffffffu, vs, 0);
        float rstd = rsqrtf(vs*(1.0f/D_)+1e-5f);
        ssn[warp][lane   ] = d0*rstd*g_s[lane   ]+be_s[lane   ];
        ssn[warp][lane+32] = d1*rstd*g_s[lane+32]+be_s[lane+32];
        ssn[warp][lane+64] = d2*rstd*g_s[lane+64]+be_s[lane+64];
        ssn[warp][lane+96] = d3*rstd*g_s[lane+96]+be_s[lane+96];
    }
    __syncthreads();

    // matvec: thread = output d, 4 rows amortize weight loads
    float qa[4]={0,0,0,0}, ka[4]={0,0,0,0}, va[4]={0,0,0,0};
    #pragma unroll 4
    for(int e=0;e<D_;e++){
        float wq=w_q[e*D_+d], wk=w_k[e*D_+d], wv=w_v[e*D_+d];
        float s0=ssn[0][e], s1=ssn[1][e], s2=ssn[2][e], s3=ssn[3][e];
        qa[0]=fmaf(s0,wq,qa[0]); qa[1]=fmaf(s1,wq,qa[1]); qa[2]=fmaf(s2,wq,qa[2]); qa[3]=fmaf(s3,wq,qa[3]);
        ka[0]=fmaf(s0,wk,ka[0]); ka[1]=fmaf(s1,wk,ka[1]); ka[2]=fmaf(s2,wk,ka[2]); ka[3]=fmaf(s3,wk,ka[3]);
        va[0]=fmaf(s0,wv,va[0]); va[1]=fmaf(s1,wv,va[1]); va[2]=fmaf(s2,wv,va[2]); va[3]=fmaf(s3,wv,va[3]);
    }
    const float bq=b_q[d], bk=b_k[d], bv=b_v[d];
    #pragma unroll
    for(int r=0;r<4;r++){
        g_q[(size_t)(row0+r)*D_+d]=(qa[r]+bq)*invS;
        sk4[r][d]=ka[r]+bk;
        sv4[r][d]=va[r]+bv;
    }
    __syncthreads();

    // pack k,v into half2 layouts
    #pragma unroll
    for(int idx=d; idx<4*(D_/2); idx+=128){
        const int r = idx>>6, u = idx&63;
        const int row = row0+r;
        const int bb = row>>9, il = row&(N_-1);
        g_kh[((size_t)bb*(D_/2)+u)*N_+il] = __floats2half2_rn(sk4[r][2*u], sk4[r][2*u+1]);
        g_vh[((size_t)bb*N_+il)*(D_/2)+u] = __floats2half2_rn(sv4[r][2*u], sv4[r][2*u+1]);
    }
}

// ---------------- Kernel B: fused attention + epilogues, 256 thr/row --------
__global__ void __launch_bounds__(256, 4) main_kernel(
    const float* __restrict__ scalar, const float* __restrict__ vector,
    const float* __restrict__ coords,
    const float* __restrict__ w_d1, const float* __restrict__ b_d1,
    const float* __restrict__ w_d2, const float* __restrict__ b_d2,
    const float* __restrict__ w_g,  const float* __restrict__ b_g,
    const float* __restrict__ w_o,  const float* __restrict__ b_o,
    const float* __restrict__ w_f1, const float* __restrict__ b_f1,
    const float* __restrict__ w_f2, const float* __restrict__ b_f2,
    const float* __restrict__ w_vo, const float* __restrict__ b_vo,
    const float* __restrict__ g_s,  const float* __restrict__ be_s,
    const float* __restrict__ g_v_, const float* __restrict__ be_v,
    float* __restrict__ out_scalar, float* __restrict__ out_vector)
{
    __shared__ float sq[D_];
    __shared__ float scoord[N_*3];
    __shared__ float sdist[N_], srd[N_], slog[N_];
    __shared__ float sQC[12];
    __shared__ float sMm[8][11], sMtot[11], sMn[10];
    __shared__ float sVp[4][D_];
    __shared__ float sH[D_], sbuf[D_], sscal[D_], shn[D_], sf[2*D_];
    __shared__ float spart[256];
    __shared__ float svagg4[192], sdirp[24], sdir[3], sgate[V_], sagg[48], svagg[48];
    __shared__ float red[8];

    const int row  = blockIdx.x;
    const int b    = row >> 9;
    const int i    = row & (N_-1);
    const int tid  = threadIdx.x;
    const int warp = tid>>5, lane = tid&31;

    if(tid<D_) sq[tid] = g_q[(size_t)row*D_+tid];
    const float* cb = coords + (size_t)b*N_*3;
    for(int t=tid; t<N_*3; t+=256) scoord[t]=cb[t];
    __syncthreads();

    const float ci0 = scoord[i*3+0], ci1 = scoord[i*3+1], ci2 = scoord[i*3+2];

    // ---- pre-pass: dists + reciprocals ----
    for(int j=tid; j<N_; j+=256){
        float dx = ci0 - scoord[j*3+0];
        float dy = ci1 - scoord[j*3+1];
        float dz = ci2 - scoord[j*3+2];
        float dist = sqrtf(fmaf(dx,dx,fmaf(dy,dy,dz*dz)));
        sdist[j] = dist;
        srd[j]   = __fdividef(1.0f, fmaxf(dist, 1e-6f));
    }
    // ---- qc reductions: 12 dots sq . Wc[:,m] ----
    for(int m=warp; m<12; m+=8){
        float a=0.f;
        #pragma unroll
        for(int c=0;c<4;c++){
            int d = lane + 32*c;
            a = fmaf(sq[d], g_Wc[d*12+m], a);
        }
        a = warpSum(a);
        if(lane==0) sQC[m]=a;
    }
    __syncthreads();

    const float biasv = sQC[0] + sQC[11];
    float qcr[10];
    #pragma unroll
    for(int p=0;p<10;p++) qcr[p]=sQC[p+1];

    const __half2* khb = g_kh + (size_t)b*(D_/2)*N_;
    const __half2* vhb = g_vh + (size_t)b*N_*(D_/2);
    const float*  vecb = vector + (size_t)b*N_*3*V_;

    // ---- pass 1: lane = j. Each warp: 32 j's, two chunks ----
    float M[11];
    #pragma unroll
    for(int m=0;m<11;m++) M[m]=0.f;

    #pragma unroll
    for(int chunk=0; chunk<2; chunk++){
        const int j = warp*32 + lane + chunk*256;
        const __half2* kcol = khb + j;
        float p0=0.f,p1=0.f,p2=0.f,p3=0.f;
        #pragma unroll 8
        for(int u=0; u<D_/2; u+=2){
            float2 a = __half22float2(kcol[(size_t)(u+0)*N_]);
            float2 c = __half22float2(kcol[(size_t)(u+1)*N_]);
            p0 = fmaf(sq[2*u+0], a.x, p0);
            p1 = fmaf(sq[2*u+1], a.y, p1);
            p2 = fmaf(sq[2*u+2], c.x, p2);
            p3 = fmaf(sq[2*u+3], c.y, p3);
        }
        const float dist = sdist[j];
        float pol = qcr[9];
        #pragma unroll
        for(int p=8;p>=0;p--) pol = fmaf(pol, dist, qcr[p]);
        pol *= dist;
        float logit = ((p0+p1)+(p2+p3)) + pol + biasv;
        float e = __expf(logit);
        slog[j]=e;
        M[10] += e;
        float t = dist;
        #pragma unroll
        for(int p=0;p<10;p++){ M[p] = fmaf(e, t, M[p]); t *= dist; }
    }
    #pragma unroll
    for(int o=16;o;o>>=1){
        #pragma unroll
        for(int m=0;m<11;m++) M[m] += __shfl_down_sync(0xffffffffu, M[m], o);
    }
    if(lane==0){
        #pragma unroll
        for(int m=0;m<11;m++) sMm[warp][m]=M[m];
    }
    __syncthreads();
    if(tid<11){
        float s = ((sMm[0][tid]+sMm[1][tid])+(sMm[2][tid]+sMm[3][tid]))
                + ((sMm[4][tid]+sMm[5][tid])+(sMm[6][tid]+sMm[7][tid]));
        sMtot[tid]=s;
    }
    __syncthreads();
    const float inv = 1.0f/sMtot[10];
    if(tid<10) sMn[tid] = sMtot[tid]*inv;

    // ---- pass 2: V accumulation, thread = (d-pair u, j-quarter jq) ----
    {
        const int u = tid & 63, jq = tid >> 6;
        const int j0 = jq*128;
        float a0=0.f,a1=0.f;
        #pragma unroll 8
        for(int jj=0; jj<128; jj++){
            const int j = j0+jj;
            float2 vf = __half22float2(vhb[(size_t)j*(D_/2)+u]);
            float e = slog[j];
            a0 = fmaf(e, vf.x, a0);
            a1 = fmaf(e, vf.y, a1);
        }
        sVp[jq][2*u  ]=a0;
        sVp[jq][2*u+1]=a1;
    }
    __syncthreads();
    float Vd = 0.0f;
    if(tid<D_) Vd = ((sVp[0][tid]+sVp[1][tid])+(sVp[2][tid]+sVp[3][tid]))*inv;

    // ---- H reconstruction from moments (tid<128) ----
    if(tid<D_){
        float C[11];
        gelu_coeffs(w_d1[tid], b_d1[tid], C);
        float Hd = C[0];
        #pragma unroll
        for(int p=1;p<11;p++) Hd = fmaf(C[p], sMn[p-1], Hd);
        sH[tid]=Hd;
    }

    // ---- vector aggregation (192 thr) + direction aggregation (24 thr) ----
    if(tid < 192){
        const int g4 = tid/48, t48 = tid - g4*48;
        const int j0 = g4*128;
        float a0=0,a1=0;
        #pragma unroll 4
        for(int j=j0;j<j0+128;j+=2){
            a0 = fmaf(slog[j],   vecb[(size_t)j*48+t48],     a0);
            a1 = fmaf(slog[j+1], vecb[(size_t)(j+1)*48+t48], a1);
        }
        svagg4[tid]=a0+a1;
    } else if(tid < 216){
        const int idx = tid-192, c = idx>>3, g = idx&7;
        const float cic = scoord[i*3+c];
        float acc=0.0f;
        for(int j=g;j<N_;j+=8){
            acc = fmaf(slog[j]*srd[j], cic - scoord[j*3+c], acc);
        }
        sdirp[idx]=acc;
    }
    __syncthreads();
    if(tid<48) svagg[tid]=(((svagg4[tid]+svagg4[tid+48])+(svagg4[tid+96]+svagg4[tid+144])))*inv;
    if(tid<3){
        float a=0;
        #pragma unroll
        for(int g=0;g<8;g++) a+=sdirp[tid*8+g];
        sdir[tid]=a*inv;
    }
    __syncthreads();

    // ---- upd = attn@v + H@w_d2 + b_d2  (split-K over 256 threads) ----
    {
        const int od = tid & 127, hf = tid >> 7;
        const int e0 = hf*64;
        float u0=0,u1=0;
        #pragma unroll 8
        for(int e=e0;e<e0+64;e+=2){
            u0 = fmaf(sH[e+0], w_d2[(e+0)*D_+od], u0);
            u1 = fmaf(sH[e+1], w_d2[(e+1)*D_+od], u1);
        }
        spart[tid]=u0+u1;
    }
    __syncthreads();
    if(tid<D_) sbuf[tid] = Vd + b_d2[tid] + spart[tid]+spart[tid+128];
    __syncthreads();

    // ---- scalar1 = scalar + upd@w_o + b_o  (split-K) ----
    {
        const int od = tid & 127, hf = tid >> 7;
        const int e0 = hf*64;
        float u0=0,u1=0;
        #pragma unroll 8
        for(int e=e0;e<e0+64;e+=2){
            u0 = fmaf(sbuf[e+0], w_o[(e+0)*D_+od], u0);
            u1 = fmaf(sbuf[e+1], w_o[(e+1)*D_+od], u1);
        }
        spart[tid]=u0+u1;
    }
    __syncthreads();
    float s1 = 0.0f;
    if(tid<D_){
        s1 = scalar[(size_t)row*D_+tid] + b_o[tid] + spart[tid]+spart[tid+128];
        sscal[tid]=s1;
    }

    // ---- LN ----
    float xc = (tid<D_)? s1 : 0.0f;
    float m  = blockSum256(xc, red)*(1.0f/D_);
    float dvc= (tid<D_)? (s1-m) : 0.0f;
    float var= blockSum256(dvc*dvc, red)*(1.0f/D_);
    if(tid<D_){
        float hn = (s1-m)*rsqrtf(var+1e-5f)*g_s[tid] + be_s[tid];
        shn[tid]=hn;
    }
    __syncthreads();

    // ---- FFN layer 1: one output per thread ----
    {
        const int m2 = tid;
        float u0=0,u1=0,u2=0,u3=0;
        #pragma unroll 4
        for(int e=0;e<D_;e+=4){
            u0 = fmaf(shn[e+0], w_f1[(e+0)*2*D_+m2], u0);
            u1 = fmaf(shn[e+1], w_f1[(e+1)*2*D_+m2], u1);
            u2 = fmaf(shn[e+2], w_f1[(e+2)*2*D_+m2], u2);
            u3 = fmaf(shn[e+3], w_f1[(e+3)*2*D_+m2], u3);
        }
        sf[m2]=geluf(b_f1[m2] + (u0+u1)+(u2+u3));
    }
    __syncthreads();

    // ---- FFN layer 2 (split-K, K=256) ----
    {
        const int od = tid & 127, hf = tid >> 7;
        const int e0 = hf*128;
        float u0=0,u1=0;
        #pragma unroll 8
        for(int e=e0;e<e0+128;e+=2){
            u0 = fmaf(sf[e+0], w_f2[(e+0)*D_+od], u0);
            u1 = fmaf(sf[e+1], w_f2[(e+1)*D_+od], u1);
        }
        spart[tid]=u0+u1;
    }
    __syncthreads();
    if(tid<D_){
        float s2 = sscal[tid] + b_f2[tid] + spart[tid]+spart[tid+128];
        out_scalar[(size_t)row*D_+tid] = s2;
        sscal[tid] = s2;
    }
    __syncthreads();

    // ---- gate ----
    if(tid<V_){
        float u0=0,u1=0,u2=0,u3=0;
        #pragma unroll 4
        for(int d2=0;d2<D_;d2+=4){
            u0 = fmaf(sscal[d2+0], w_g[(d2+0)*V_+tid], u0);
            u1 = fmaf(sscal[d2+1], w_g[(d2+1)*V_+tid], u1);
            u2 = fmaf(sscal[d2+2], w_g[(d2+2)*V_+tid], u2);
            u3 = fmaf(sscal[d2+3], w_g[(d2+3)*V_+tid], u3);
        }
        float a = b_g[tid] + (u0+u1)+(u2+u3);
        sgate[tid] = 1.0f/(1.0f+__expf(-a));
    }
    __syncthreads();

    // ---- agg, LN over V, proj, vector residual ----
    if(tid<48){
        int c = tid>>4, vv = tid&15;
        sagg[tid] = svagg[tid] + sdir[c]*sgate[vv];
    }
    __syncthreads();
    if(tid<48){
        int c = tid>>4, vv = tid&15;
        float m2=0.0f;
        #pragma unroll
        for(int u=0;u<V_;u++) m2 += sagg[c*V_+u];
        m2 *= (1.0f/V_);
        float var2=0.0f;
        #pragma unroll
        for(int u=0;u<V_;u++){ float d3=sagg[c*V_+u]-m2; var2 += d3*d3; }
        var2 *= (1.0f/V_);
        float invr = rsqrtf(var2+1e-5f);
        float acc = b_vo[vv];
        #pragma unroll
        for(int u=0;u<V_;u++){
            float lnu = (sagg[c*V_+u]-m2)*invr*g_v_[u] + be_v[u];
            acc = fmaf(lnu, w_vo[u*V_+vv], acc);
        }
        out_vector[(size_t)row*3*V_+tid] = vecb[(size_t)i*3*V_+tid] + acc;
    }
}

extern "C" void kernel_launch(void* const* d_in, const int* in_sizes, int n_in,
                              void* d_out, int out_size)
{
    const float* scalar = (const float*)d_in[0];
    const float* vector = (const float*)d_in[1];
    const float* coords = (const float*)d_in[2];
    const float* w_q  = (const float*)d_in[3];  const float* b_q  = (const float*)d_in[4];
    const float* w_k  = (const float*)d_in[5];  const float* b_k  = (const float*)d_in[6];
    const float* w_v  = (const float*)d_in[7];  const float* b_v  = (const float*)d_in[8];
    const float* w_d1 = (const float*)d_in[9];  const float* b_d1 = (const float*)d_in[10];
    const float* w_d2 = (const float*)d_in[11]; const float* b_d2 = (const float*)d_in[12];
    const float* w_g  = (const float*)d_in[13]; const float* b_g  = (const float*)d_in[14];
    const float* w_o  = (const float*)d_in[15]; const float* b_o  = (const float*)d_in[16];
    const float* w_f1 = (const float*)d_in[17]; const float* b_f1 = (const float*)d_in[18];
    const float* w_f2 = (const float*)d_in[19]; const float* b_f2 = (const float*)d_in[20];
    const float* w_vo = (const float*)d_in[21]; const float* b_vo = (const float*)d_in[22];
    const float* g_s  = (const float*)d_in[23]; const float* be_s = (const float*)d_in[24];
    const float* g_v  = (const float*)d_in[25]; const float* be_v = (const float*)d_in[26];

    float* out = (float*)d_out;
    float* out_scalar = out;
    float* out_vector = out + (size_t)ROWS*D_;

    prep_kernel<<<ROWS/4 + 1,128>>>(scalar, w_q,b_q, w_k,b_k, w_v,b_v,
                                    w_d1,b_d1, w_d2,b_d2, g_s,be_s);
    main_kernel<<<ROWS,256>>>(scalar, vector, coords,
                              w_d1,b_d1, w_d2,b_d2, w_g,b_g, w_o,b_o,
                              w_f1,b_f1, w_f2,b_f2, w_vo,b_vo,
                              g_s,be_s, g_v,be_v,
                              out_scalar, out_vector);
}

// round 9
// speedup vs baseline: 2.0321x; 1.0431x over previous
#include <cuda_runtime.h>
#include <cuda_fp16.h>
#include <math.h>

#define B_ 2
#define N_ 512
#define D_ 128
#define V_ 16
#define ROWS (B_*N_)

// scratch (allocation-free rule: __device__ globals)
__device__ float   g_q  [ROWS*D_];       // q * invS
__device__ __half2 g_kh [B_*(D_/2)*N_];  // [b][u][j] = (k[2u][j], k[2u+1][j])
__device__ __half2 g_vh [B_*N_*(D_/2)];  // [b][j][u] = (v[2u], v[2u+1])
__device__ float   g_Wc [D_*12];         // Wc[d][p] p=0..10, col 11 = b_d2[d]

__device__ __forceinline__ float geluf(float x){
    return 0.5f*x*(1.0f+erff(x*0.70710678118654752f));
}
// polynomial coefficients of gelu_fast(w*t+b) in powers of t (degree 10)
__device__ __forceinline__ void gelu_coeffs(float w, float b, float C[11]){
    const float K  = 0.3989422804014327f;
    const float c2 = K;
    const float c4 = K*-0.16666666666667f;
    const float c6 = K*0.025f;
    const float c8 = K*-2.9761904761905e-3f;
    const float c10= K*2.8935185185185e-4f;
    float wp[11], bp[11];
    wp[0]=1.f; bp[0]=1.f;
    #pragma unroll
    for(int t=1;t<11;t++){ wp[t]=wp[t-1]*w; bp[t]=bp[t-1]*b; }
    #pragma unroll
    for(int p=0;p<11;p++) C[p]=0.f;
    C[0] += 0.5f*b; C[1] += 0.5f*w;
    const float B2[3]={1,2,1};
    const float B4[5]={1,4,6,4,1};
    const float B6[7]={1,6,15,20,15,6,1};
    const float B8[9]={1,8,28,56,70,56,28,8,1};
    const float B10[11]={1,10,45,120,210,252,210,120,45,10,1};
    #pragma unroll
    for(int p=0;p<=2;p++)  C[p] += c2 *B2[p] *wp[p]*bp[2-p];
    #pragma unroll
    for(int p=0;p<=4;p++)  C[p] += c4 *B4[p] *wp[p]*bp[4-p];
    #pragma unroll
    for(int p=0;p<=6;p++)  C[p] += c6 *B6[p] *wp[p]*bp[6-p];
    #pragma unroll
    for(int p=0;p<=8;p++)  C[p] += c8 *B8[p] *wp[p]*bp[8-p];
    #pragma unroll
    for(int p=0;p<=10;p++) C[p] += c10*B10[p]*wp[p]*bp[10-p];
}
__device__ __forceinline__ float warpSum(float v){
    #pragma unroll
    for(int o=16;o;o>>=1) v += __shfl_down_sync(0xffffffffu, v, o);
    return v;
}
// 256-thread block reduction (main kernel)
__device__ __forceinline__ float blockSum256(float v, float* red){
    int w = threadIdx.x>>5, l = threadIdx.x&31;
    v = warpSum(v);
    if(l==0) red[w]=v;
    __syncthreads();
    if(threadIdx.x==0){
        float s = 0.f;
        #pragma unroll
        for(int k=0;k<8;k++) s += red[k];
        red[0]=s;
    }
    __syncthreads();
    float r = red[0];
    __syncthreads();
    return r;
}

// ---------- Kernel A: LN + q/k/v (4 rows/blk); last block does Wc setup -----
__global__ void __launch_bounds__(128) prep_kernel(
    const float* __restrict__ scalar,
    const float* __restrict__ w_q, const float* __restrict__ b_q,
    const float* __restrict__ w_k, const float* __restrict__ b_k,
    const float* __restrict__ w_v, const float* __restrict__ b_v,
    const float* __restrict__ w_d1, const float* __restrict__ b_d1,
    const float* __restrict__ w_d2, const float* __restrict__ b_d2,
    const float* __restrict__ g_s, const float* __restrict__ be_s)
{
    __shared__ float ssn[4][D_];
    __shared__ float sk4[4][D_], sv4[4][D_];
    __shared__ float sC[11][D_];
    const int d = threadIdx.x;

    if(blockIdx.x == ROWS/4){
        // ---- setup: Wc = W_d2^T C^T ----
        {
            float C[11];
            gelu_coeffs(w_d1[d], b_d1[d], C);
            #pragma unroll
            for(int p=0;p<11;p++) sC[p][d]=C[p];
        }
        __syncthreads();
        float acc[11];
        #pragma unroll
        for(int p=0;p<11;p++) acc[p]=0.f;
        #pragma unroll 4
        for(int e=0;e<D_;e++){
            float w = w_d2[e*D_+d];
            #pragma unroll
            for(int p=0;p<11;p++) acc[p] = fmaf(sC[p][e], w, acc[p]);
        }
        #pragma unroll
        for(int p=0;p<11;p++) g_Wc[d*12+p]=acc[p];
        g_Wc[d*12+11]=b_d2[d];
        return;
    }

    const int row0 = blockIdx.x*4;
    const int warp = d>>5, lane = d&31;
    const float invS = 0.0883883476483184f; // 1/sqrt(128)

    // LN: warp r handles row row0+r
    {
        const float* xr = scalar + (size_t)(row0+warp)*D_;
        float v0=xr[lane], v1=xr[lane+32], v2=xr[lane+64], v3=xr[lane+96];
        float s = (v0+v1)+(v2+v3);
        s = warpSum(s); s = __shfl_sync(0xffffffffu, s, 0);
        float m = s*(1.0f/D_);
        float d0=v0-m, d1=v1-m, d2=v2-m, d3=v3-m;
        float vs = (d0*d0+d1*d1)+(d2*d2+d3*d3);
        vs = warpSum(vs); vs = __shfl_sync(0xffffffffu, vs, 0);
        float rstd = rsqrtf(vs*(1.0f/D_)+1e-5f);
        ssn[warp][lane   ] = d0*rstd*g_s[lane   ]+be_s[lane   ];
        ssn[warp][lane+32] = d1*rstd*g_s[lane+32]+be_s[lane+32];
        ssn[warp][lane+64] = d2*rstd*g_s[lane+64]+be_s[lane+64];
        ssn[warp][lane+96] = d3*rstd*g_s[lane+96]+be_s[lane+96];
    }
    __syncthreads();

    // matvec: thread = output d, 4 rows amortize weight loads
    float qa[4]={0,0,0,0}, ka[4]={0,0,0,0}, va[4]={0,0,0,0};
    #pragma unroll 4
    for(int e=0;e<D_;e++){
        float wq=w_q[e*D_+d], wk=w_k[e*D_+d], wv=w_v[e*D_+d];
        float s0=ssn[0][e], s1=ssn[1][e], s2=ssn[2][e], s3=ssn[3][e];
        qa[0]=fmaf(s0,wq,qa[0]); qa[1]=fmaf(s1,wq,qa[1]); qa[2]=fmaf(s2,wq,qa[2]); qa[3]=fmaf(s3,wq,qa[3]);
        ka[0]=fmaf(s0,wk,ka[0]); ka[1]=fmaf(s1,wk,ka[1]); ka[2]=fmaf(s2,wk,ka[2]); ka[3]=fmaf(s3,wk,ka[3]);
        va[0]=fmaf(s0,wv,va[0]); va[1]=fmaf(s1,wv,va[1]); va[2]=fmaf(s2,wv,va[2]); va[3]=fmaf(s3,wv,va[3]);
    }
    const float bq=b_q[d], bk=b_k[d], bv=b_v[d];
    #pragma unroll
    for(int r=0;r<4;r++){
        g_q[(size_t)(row0+r)*D_+d]=(qa[r]+bq)*invS;
        sk4[r][d]=ka[r]+bk;
        sv4[r][d]=va[r]+bv;
    }
    __syncthreads();

    // pack k,v into half2 layouts
    #pragma unroll
    for(int idx=d; idx<4*(D_/2); idx+=128){
        const int r = idx>>6, u = idx&63;
        const int row = row0+r;
        const int bb = row>>9, il = row&(N_-1);
        g_kh[((size_t)bb*(D_/2)+u)*N_+il] = __floats2half2_rn(sk4[r][2*u], sk4[r][2*u+1]);
        g_vh[((size_t)bb*N_+il)*(D_/2)+u] = __floats2half2_rn(sv4[r][2*u], sv4[r][2*u+1]);
    }
}

// ---------------- Kernel B: fused attention + epilogues, 256 thr/row --------
__global__ void __launch_bounds__(256, 4) main_kernel(
    const float* __restrict__ scalar, const float* __restrict__ vector,
    const float* __restrict__ coords,
    const float* __restrict__ w_d1, const float* __restrict__ b_d1,
    const float* __restrict__ w_d2, const float* __restrict__ b_d2,
    const float* __restrict__ w_g,  const float* __restrict__ b_g,
    const float* __restrict__ w_o,  const float* __restrict__ b_o,
    const float* __restrict__ w_f1, const float* __restrict__ b_f1,
    const float* __restrict__ w_f2, const float* __restrict__ b_f2,
    const float* __restrict__ w_vo, const float* __restrict__ b_vo,
    const float* __restrict__ g_s,  const float* __restrict__ be_s,
    const float* __restrict__ g_v_, const float* __restrict__ be_v,
    float* __restrict__ out_scalar, float* __restrict__ out_vector)
{
    __shared__ float sq[D_];
    __shared__ float scoord[N_*3];
    __shared__ float sdist[N_], srd[N_], slog[N_];
    __shared__ float sQC[12];
    __shared__ float sMm[8][11], sMtot[11], sMn[10];
    __shared__ float sVp[4][D_];
    __shared__ float sH[D_], sbuf[D_], sscal[D_], shn[D_], sf[2*D_];
    __shared__ float spart[256];
    __shared__ float svagg4[192], sdirp[24], sdir[3], sgate[V_], sagg[48], svagg[48];
    __shared__ float red[8];

    const int row  = blockIdx.x;
    const int b    = row >> 9;
    const int i    = row & (N_-1);
    const int tid  = threadIdx.x;
    const int warp = tid>>5, lane = tid&31;

    if(tid<D_) sq[tid] = g_q[(size_t)row*D_+tid];
    const float* cb = coords + (size_t)b*N_*3;
    for(int t=tid; t<N_*3; t+=256) scoord[t]=cb[t];
    __syncthreads();

    const float ci0 = scoord[i*3+0], ci1 = scoord[i*3+1], ci2 = scoord[i*3+2];

    // ---- pre-pass: dists + reciprocals ----
    for(int j=tid; j<N_; j+=256){
        float dx = ci0 - scoord[j*3+0];
        float dy = ci1 - scoord[j*3+1];
        float dz = ci2 - scoord[j*3+2];
        float dist = sqrtf(fmaf(dx,dx,fmaf(dy,dy,dz*dz)));
        sdist[j] = dist;
        srd[j]   = __fdividef(1.0f, fmaxf(dist, 1e-6f));
    }
    // ---- qc reductions: 12 dots sq . Wc[:,m] ----
    for(int m=warp; m<12; m+=8){
        float a=0.f;
        #pragma unroll
        for(int c=0;c<4;c++){
            int d = lane + 32*c;
            a = fmaf(sq[d], g_Wc[d*12+m], a);
        }
        a = warpSum(a);
        if(lane==0) sQC[m]=a;
    }
    __syncthreads();

    const float biasv = sQC[0] + sQC[11];
    float qcr[10];
    #pragma unroll
    for(int p=0;p<10;p++) qcr[p]=sQC[p+1];

    const __half2* khb = g_kh + (size_t)b*(D_/2)*N_;
    const __half2* vhb = g_vh + (size_t)b*N_*(D_/2);
    const float*  vecb = vector + (size_t)b*N_*3*V_;

    // ---- pass 1: lane = j. Each warp: 32 j's, two chunks ----
    float M[11];
    #pragma unroll
    for(int m=0;m<11;m++) M[m]=0.f;

    #pragma unroll
    for(int chunk=0; chunk<2; chunk++){
        const int j = warp*32 + lane + chunk*256;
        const __half2* kcol = khb + j;
        float p0=0.f,p1=0.f,p2=0.f,p3=0.f;
        #pragma unroll 8
        for(int u=0; u<D_/2; u+=2){
            float2 a = __half22float2(kcol[(size_t)(u+0)*N_]);
            float2 c = __half22float2(kcol[(size_t)(u+1)*N_]);
            p0 = fmaf(sq[2*u+0], a.x, p0);
            p1 = fmaf(sq[2*u+1], a.y, p1);
            p2 = fmaf(sq[2*u+2], c.x, p2);
            p3 = fmaf(sq[2*u+3], c.y, p3);
        }
        const float dist = sdist[j];
        float pol = qcr[9];
        #pragma unroll
        for(int p=8;p>=0;p--) pol = fmaf(pol, dist, qcr[p]);
        pol *= dist;
        float logit = ((p0+p1)+(p2+p3)) + pol + biasv;
        float e = __expf(logit);
        slog[j]=e;
        M[10] += e;
        float t = dist;
        #pragma unroll
        for(int p=0;p<10;p++){ M[p] = fmaf(e, t, M[p]); t *= dist; }
    }
    #pragma unroll
    for(int o=16;o;o>>=1){
        #pragma unroll
        for(int m=0;m<11;m++) M[m] += __shfl_down_sync(0xffffffffu, M[m], o);
    }
    if(lane==0){
        #pragma unroll
        for(int m=0;m<11;m++) sMm[warp][m]=M[m];
    }
    __syncthreads();
    if(tid<11){
        float s = ((sMm[0][tid]+sMm[1][tid])+(sMm[2][tid]+sMm[3][tid]))
                + ((sMm[4][tid]+sMm[5][tid])+(sMm[6][tid]+sMm[7][tid]));
        sMtot[tid]=s;
    }
    __syncthreads();
    const float inv = 1.0f/sMtot[10];
    if(tid<10) sMn[tid] = sMtot[tid]*inv;

    // ---- pass 2: V accumulation, thread = (d-pair u, j-quarter jq) ----
    {
        const int u = tid & 63, jq = tid >> 6;
        const int j0 = jq*128;
        float a0=0.f,a1=0.f;
        #pragma unroll 8
        for(int jj=0; jj<128; jj++){
            const int j = j0+jj;
            float2 vf = __half22float2(vhb[(size_t)j*(D_/2)+u]);
            float e = slog[j];
            a0 = fmaf(e, vf.x, a0);
            a1 = fmaf(e, vf.y, a1);
        }
        sVp[jq][2*u  ]=a0;
        sVp[jq][2*u+1]=a1;
    }
    __syncthreads();
    float Vd = 0.0f;
    if(tid<D_) Vd = ((sVp[0][tid]+sVp[1][tid])+(sVp[2][tid]+sVp[3][tid]))*inv;

    // ---- H reconstruction from moments (tid<128) ----
    if(tid<D_){
        float C[11];
        gelu_coeffs(w_d1[tid], b_d1[tid], C);
        float Hd = C[0];
        #pragma unroll
        for(int p=1;p<11;p++) Hd = fmaf(C[p], sMn[p-1], Hd);
        sH[tid]=Hd;
    }

    // ---- vector aggregation (192 thr) + direction aggregation (24 thr) ----
    if(tid < 192){
        const int g4 = tid/48, t48 = tid - g4*48;
        const int j0 = g4*128;
        float a0=0,a1=0;
        #pragma unroll 4
        for(int j=j0;j<j0+128;j+=2){
            a0 = fmaf(slog[j],   vecb[(size_t)j*48+t48],     a0);
            a1 = fmaf(slog[j+1], vecb[(size_t)(j+1)*48+t48], a1);
        }
        svagg4[tid]=a0+a1;
    } else if(tid < 216){
        const int idx = tid-192, c = idx>>3, g = idx&7;
        const float cic = scoord[i*3+c];
        float acc=0.0f;
        for(int j=g;j<N_;j+=8){
            acc = fmaf(slog[j]*srd[j], cic - scoord[j*3+c], acc);
        }
        sdirp[idx]=acc;
    }
    __syncthreads();
    if(tid<48) svagg[tid]=(((svagg4[tid]+svagg4[tid+48])+(svagg4[tid+96]+svagg4[tid+144])))*inv;
    if(tid<3){
        float a=0;
        #pragma unroll
        for(int g=0;g<8;g++) a+=sdirp[tid*8+g];
        sdir[tid]=a*inv;
    }
    __syncthreads();

    // ---- upd = attn@v + H@w_d2 + b_d2  (split-K over 256 threads) ----
    {
        const int od = tid & 127, hf = tid >> 7;
        const int e0 = hf*64;
        float u0=0,u1=0;
        #pragma unroll 8
        for(int e=e0;e<e0+64;e+=2){
            u0 = fmaf(sH[e+0], w_d2[(e+0)*D_+od], u0);
            u1 = fmaf(sH[e+1], w_d2[(e+1)*D_+od], u1);
        }
        spart[tid]=u0+u1;
    }
    __syncthreads();
    if(tid<D_) sbuf[tid] = Vd + b_d2[tid] + spart[tid]+spart[tid+128];
    __syncthreads();

    // ---- scalar1 = scalar + upd@w_o + b_o  (split-K) ----
    {
        const int od = tid & 127, hf = tid >> 7;
        const int e0 = hf*64;
        float u0=0,u1=0;
        #pragma unroll 8
        for(int e=e0;e<e0+64;e+=2){
            u0 = fmaf(sbuf[e+0], w_o[(e+0)*D_+od], u0);
            u1 = fmaf(sbuf[e+1], w_o[(e+1)*D_+od], u1);
        }
        spart[tid]=u0+u1;
    }
    __syncthreads();
    float s1 = 0.0f;
    if(tid<D_){
        s1 = scalar[(size_t)row*D_+tid] + b_o[tid] + spart[tid]+spart[tid+128];
        sscal[tid]=s1;
    }

    // ---- LN ----
    float xc = (tid<D_)? s1 : 0.0f;
    float m  = blockSum256(xc, red)*(1.0f/D_);
    float dvc= (tid<D_)? (s1-m) : 0.0f;
    float var= blockSum256(dvc*dvc, red)*(1.0f/D_);
    if(tid<D_){
        float hn = (s1-m)*rsqrtf(var+1e-5f)*g_s[tid] + be_s[tid];
        shn[tid]=hn;
    }
    __syncthreads();

    // ---- FFN layer 1: one output per thread ----
    {
        const int m2 = tid;
        float u0=0,u1=0,u2=0,u3=0;
        #pragma unroll 4
        for(int e=0;e<D_;e+=4){
            u0 = fmaf(shn[e+0], w_f1[(e+0)*2*D_+m2], u0);
            u1 = fmaf(shn[e+1], w_f1[(e+1)*2*D_+m2], u1);
            u2 = fmaf(shn[e+2], w_f1[(e+2)*2*D_+m2], u2);
            u3 = fmaf(shn[e+3], w_f1[(e+3)*2*D_+m2], u3);
        }
        sf[m2]=geluf(b_f1[m2] + (u0+u1)+(u2+u3));
    }
    __syncthreads();

    // ---- FFN layer 2 (split-K, K=256) ----
    {
        const int od = tid & 127, hf = tid >> 7;
        const int e0 = hf*128;
        float u0=0,u1=0;
        #pragma unroll 8
        for(int e=e0;e<e0+128;e+=2){
            u0 = fmaf(sf[e+0], w_f2[(e+0)*D_+od], u0);
            u1 = fmaf(sf[e+1], w_f2[(e+1)*D_+od], u1);
        }
        spart[tid]=u0+u1;
    }
    __syncthreads();
    if(tid<D_){
        float s2 = sscal[tid] + b_f2[tid] + spart[tid]+spart[tid+128];
        out_scalar[(size_t)row*D_+tid] = s2;
        sscal[tid] = s2;
    }
    __syncthreads();

    // ---- gate ----
    if(tid<V_){
        float u0=0,u1=0,u2=0,u3=0;
        #pragma unroll 4
        for(int d2=0;d2<D_;d2+=4){
            u0 = fmaf(sscal[d2+0], w_g[(d2+0)*V_+tid], u0);
            u1 = fmaf(sscal[d2+1], w_g[(d2+1)*V_+tid], u1);
            u2 = fmaf(sscal[d2+2], w_g[(d2+2)*V_+tid], u2);
            u3 = fmaf(sscal[d2+3], w_g[(d2+3)*V_+tid], u3);
        }
        float a = b_g[tid] + (u0+u1)+(u2+u3);
        sgate[tid] = 1.0f/(1.0f+__expf(-a));
    }
    __syncthreads();

    // ---- agg, LN over V, proj, vector residual ----
    if(tid<48){
        int c = tid>>4, vv = tid&15;
        sagg[tid] = svagg[tid] + sdir[c]*sgate[vv];
    }
    __syncthreads();
    if(tid<48){
        int c = tid>>4, vv = tid&15;
        float m2=0.0f;
        #pragma unroll
        for(int u=0;u<V_;u++) m2 += sagg[c*V_+u];
        m2 *= (1.0f/V_);
        float var2=0.0f;
        #pragma unroll
        for(int u=0;u<V_;u++){ float d3=sagg[c*V_+u]-m2; var2 += d3*d3; }
        var2 *= (1.0f/V_);
        float invr = rsqrtf(var2+1e-5f);
        float acc = b_vo[vv];
        #pragma unroll
        for(int u=0;u<V_;u++){
            float lnu = (sagg[c*V_+u]-m2)*invr*g_v_[u] + be_v[u];
            acc = fmaf(lnu, w_vo[u*V_+vv], acc);
        }
        out_vector[(size_t)row*3*V_+tid] = vecb[(size_t)i*3*V_+tid] + acc;
    }
}

extern "C" void kernel_launch(void* const* d_in, const int* in_sizes, int n_in,
                              void* d_out, int out_size)
{
    const float* scalar = (const float*)d_in[0];
    const float* vector = (const float*)d_in[1];
    const float* coords = (const float*)d_in[2];
    const float* w_q  = (const float*)d_in[3];  const float* b_q  = (const float*)d_in[4];
    const float* w_k  = (const float*)d_in[5];  const float* b_k  = (const float*)d_in[6];
    const float* w_v  = (const float*)d_in[7];  const float* b_v  = (const float*)d_in[8];
    const float* w_d1 = (const float*)d_in[9];  const float* b_d1 = (const float*)d_in[10];
    const float* w_d2 = (const float*)d_in[11]; const float* b_d2 = (const float*)d_in[12];
    const float* w_g  = (const float*)d_in[13]; const float* b_g  = (const float*)d_in[14];
    const float* w_o  = (const float*)d_in[15]; const float* b_o  = (const float*)d_in[16];
    const float* w_f1 = (const float*)d_in[17]; const float* b_f1 = (const float*)d_in[18];
    const float* w_f2 = (const float*)d_in[19]; const float* b_f2 = (const float*)d_in[20];
    const float* w_vo = (const float*)d_in[21]; const float* b_vo = (const float*)d_in[22];
    const float* g_s  = (const float*)d_in[23]; const float* be_s = (const float*)d_in[24];
    const float* g_v  = (const float*)d_in[25]; const float* be_v = (const float*)d_in[26];

    float* out = (float*)d_out;
    float* out_scalar = out;
    float* out_vector = out + (size_t)ROWS*D_;

    prep_kernel<<<ROWS/4 + 1,128>>>(scalar, w_q,b_q, w_k,b_k, w_v,b_v,
                                    w_d1,b_d1, w_d2,b_d2, g_s,be_s);
    main_kernel<<<ROWS,256>>>(scalar, vector, coords,
                              w_d1,b_d1, w_d2,b_d2, w_g,b_g, w_o,b_o,
                              w_f1,b_f1, w_f2,b_f2, w_vo,b_vo,
                              g_s,be_s, g_v,be_v,
                              out_scalar, out_vector);
}

// round 10
// speedup vs baseline: 2.1413x; 1.0537x over previous
#include <cuda_runtime.h>
#include <cuda_fp16.h>
#include <math.h>

#define B_ 2
#define N_ 512
#define D_ 128
#define V_ 16
#define ROWS (B_*N_)

// scratch (allocation-free rule: __device__ globals)
__device__ float   g_q  [ROWS*D_];       // q * invS
__device__ __half2 g_kh [B_*(D_/2)*N_];  // [b][u][j] = (k[2u][j], k[2u+1][j])
__device__ __half2 g_vh [B_*N_*(D_/2)];  // [b][j][u] = (v[2u], v[2u+1])
__device__ float   g_Wc [D_*12];         // Wc[d][p] p=0..10, col 11 = b_d2[d]

__device__ __forceinline__ float geluf(float x){
    return 0.5f*x*(1.0f+erff(x*0.70710678118654752f));
}
// polynomial coefficients of gelu_fast(w*t+b) in powers of t (degree 10)
__device__ __forceinline__ void gelu_coeffs(float w, float b, float C[11]){
    const float K  = 0.3989422804014327f;
    const float c2 = K;
    const float c4 = K*-0.16666666666667f;
    const float c6 = K*0.025f;
    const float c8 = K*-2.9761904761905e-3f;
    const float c10= K*2.8935185185185e-4f;
    float wp[11], bp[11];
    wp[0]=1.f; bp[0]=1.f;
    #pragma unroll
    for(int t=1;t<11;t++){ wp[t]=wp[t-1]*w; bp[t]=bp[t-1]*b; }
    #pragma unroll
    for(int p=0;p<11;p++) C[p]=0.f;
    C[0] += 0.5f*b; C[1] += 0.5f*w;
    const float B2[3]={1,2,1};
    const float B4[5]={1,4,6,4,1};
    const float B6[7]={1,6,15,20,15,6,1};
    const float B8[9]={1,8,28,56,70,56,28,8,1};
    const float B10[11]={1,10,45,120,210,252,210,120,45,10,1};
    #pragma unroll
    for(int p=0;p<=2;p++)  C[p] += c2 *B2[p] *wp[p]*bp[2-p];
    #pragma unroll
    for(int p=0;p<=4;p++)  C[p] += c4 *B4[p] *wp[p]*bp[4-p];
    #pragma unroll
    for(int p=0;p<=6;p++)  C[p] += c6 *B6[p] *wp[p]*bp[6-p];
    #pragma unroll
    for(int p=0;p<=8;p++)  C[p] += c8 *B8[p] *wp[p]*bp[8-p];
    #pragma unroll
    for(int p=0;p<=10;p++) C[p] += c10*B10[p]*wp[p]*bp[10-p];
}
__device__ __forceinline__ float warpSum(float v){
    #pragma unroll
    for(int o=16;o;o>>=1) v += __shfl_down_sync(0xffffffffu, v, o);
    return v;
}
// dual 128-thread block reduction
__device__ __forceinline__ void blockSum2(float& v0, float& v1, float* red){
    int w = threadIdx.x>>5, l = threadIdx.x&31;
    #pragma unroll
    for(int o=16;o;o>>=1){
        v0 += __shfl_down_sync(0xffffffffu, v0, o);
        v1 += __shfl_down_sync(0xffffffffu, v1, o);
    }
    if(l==0){ red[w]=v0; red[4+w]=v1; }
    __syncthreads();
    v0 = (red[0]+red[1])+(red[2]+red[3]);
    v1 = (red[4]+red[5])+(red[6]+red[7]);
    __syncthreads();
}

// ---------- Kernel A: LN + q/k/v (4 rows/blk); last block does Wc setup -----
__global__ void __launch_bounds__(128) prep_kernel(
    const float* __restrict__ scalar,
    const float* __restrict__ w_q, const float* __restrict__ b_q,
    const float* __restrict__ w_k, const float* __restrict__ b_k,
    const float* __restrict__ w_v, const float* __restrict__ b_v,
    const float* __restrict__ w_d1, const float* __restrict__ b_d1,
    const float* __restrict__ w_d2, const float* __restrict__ b_d2,
    const float* __restrict__ g_s, const float* __restrict__ be_s)
{
    __shared__ float ssn[4][D_];
    __shared__ float sk4[4][D_], sv4[4][D_];
    __shared__ float sC[11][D_];
    const int d = threadIdx.x;

    if(blockIdx.x == ROWS/4){
        {
            float C[11];
            gelu_coeffs(w_d1[d], b_d1[d], C);
            #pragma unroll
            for(int p=0;p<11;p++) sC[p][d]=C[p];
        }
        __syncthreads();
        float acc[11];
        #pragma unroll
        for(int p=0;p<11;p++) acc[p]=0.f;
        #pragma unroll 4
        for(int e=0;e<D_;e++){
            float w = w_d2[e*D_+d];
            #pragma unroll
            for(int p=0;p<11;p++) acc[p] = fmaf(sC[p][e], w, acc[p]);
        }
        #pragma unroll
        for(int p=0;p<11;p++) g_Wc[d*12+p]=acc[p];
        g_Wc[d*12+11]=b_d2[d];
        return;
    }

    const int row0 = blockIdx.x*4;
    const int warp = d>>5, lane = d&31;
    const float invS = 0.0883883476483184f; // 1/sqrt(128)

    {
        const float* xr = scalar + (size_t)(row0+warp)*D_;
        float v0=xr[lane], v1=xr[lane+32], v2=xr[lane+64], v3=xr[lane+96];
        float s = (v0+v1)+(v2+v3);
        s = warpSum(s); s = __shfl_sync(0xffffffffu, s, 0);
        float m = s*(1.0f/D_);
        float d0=v0-m, d1=v1-m, d2=v2-m, d3=v3-m;
        float vs = (d0*d0+d1*d1)+(d2*d2+d3*d3);
        vs = warpSum(vs); vs = __shfl_sync(0xffffffffu, vs, 0);
        float rstd = rsqrtf(vs*(1.0f/D_)+1e-5f);
        ssn[warp][lane   ] = d0*rstd*g_s[lane   ]+be_s[lane   ];
        ssn[warp][lane+32] = d1*rstd*g_s[lane+32]+be_s[lane+32];
        ssn[warp][lane+64] = d2*rstd*g_s[lane+64]+be_s[lane+64];
        ssn[warp][lane+96] = d3*rstd*g_s[lane+96]+be_s[lane+96];
    }
    __syncthreads();

    float qa[4]={0,0,0,0}, ka[4]={0,0,0,0}, va[4]={0,0,0,0};
    #pragma unroll 4
    for(int e=0;e<D_;e++){
        float wq=w_q[e*D_+d], wk=w_k[e*D_+d], wv=w_v[e*D_+d];
        float s0=ssn[0][e], s1=ssn[1][e], s2=ssn[2][e], s3=ssn[3][e];
        qa[0]=fmaf(s0,wq,qa[0]); qa[1]=fmaf(s1,wq,qa[1]); qa[2]=fmaf(s2,wq,qa[2]); qa[3]=fmaf(s3,wq,qa[3]);
        ka[0]=fmaf(s0,wk,ka[0]); ka[1]=fmaf(s1,wk,ka[1]); ka[2]=fmaf(s2,wk,ka[2]); ka[3]=fmaf(s3,wk,ka[3]);
        va[0]=fmaf(s0,wv,va[0]); va[1]=fmaf(s1,wv,va[1]); va[2]=fmaf(s2,wv,va[2]); va[3]=fmaf(s3,wv,va[3]);
    }
    const float bq=b_q[d], bk=b_k[d], bv=b_v[d];
    #pragma unroll
    for(int r=0;r<4;r++){
        g_q[(size_t)(row0+r)*D_+d]=(qa[r]+bq)*invS;
        sk4[r][d]=ka[r]+bk;
        sv4[r][d]=va[r]+bv;
    }
    __syncthreads();

    #pragma unroll
    for(int idx=d; idx<4*(D_/2); idx+=128){
        const int r = idx>>6, u = idx&63;
        const int row = row0+r;
        const int bb = row>>9, il = row&(N_-1);
        g_kh[((size_t)bb*(D_/2)+u)*N_+il] = __floats2half2_rn(sk4[r][2*u], sk4[r][2*u+1]);
        g_vh[((size_t)bb*N_+il)*(D_/2)+u] = __floats2half2_rn(sv4[r][2*u], sv4[r][2*u+1]);
    }
}

// ---------------- Kernel B: 2 rows per block, 128 threads -------------------
__global__ void __launch_bounds__(128, 5) main_kernel(
    const float* __restrict__ scalar, const float* __restrict__ vector,
    const float* __restrict__ coords,
    const float* __restrict__ w_d1, const float* __restrict__ b_d1,
    const float* __restrict__ w_d2, const float* __restrict__ b_d2,
    const float* __restrict__ w_g,  const float* __restrict__ b_g,
    const float* __restrict__ w_o,  const float* __restrict__ b_o,
    const float* __restrict__ w_f1, const float* __restrict__ b_f1,
    const float* __restrict__ w_f2, const float* __restrict__ b_f2,
    const float* __restrict__ w_vo, const float* __restrict__ b_vo,
    const float* __restrict__ g_s,  const float* __restrict__ be_s,
    const float* __restrict__ g_v_, const float* __restrict__ be_v,
    float* __restrict__ out_scalar, float* __restrict__ out_vector)
{
    __shared__ float sq0[D_], sq1[D_];
    __shared__ float scoord[N_*3];
    __shared__ float sdist0[N_], sdist1[N_], srd0[N_], srd1[N_];
    __shared__ float slog0[N_], slog1[N_];
    __shared__ float sQC0[12], sQC1[12];
    __shared__ float sMm0[4][11], sMm1[4][11], sMtot0[11], sMtot1[11], sMn0[10], sMn1[10];
    __shared__ float sVp0[2][D_], sVp1[2][D_];
    __shared__ float sH0[D_], sH1[D_], sbuf0[D_], sbuf1[D_];
    __shared__ float sscal0[D_], sscal1[D_], shn0[D_], shn1[D_];
    __shared__ float sf0[2*D_], sf1[2*D_];
    __shared__ float svaggp0[96], svaggp1[96], svagg0[48], svagg1[48];
    __shared__ float sdirp[2][12], sdir0[3], sdir1[3];
    __shared__ float sgate0[V_], sgate1[V_], sagg0[48], sagg1[48];
    __shared__ float red[8];

    const int pair = blockIdx.x;
    const int row0 = pair*2, row1 = row0+1;
    const int b    = row0 >> 9;
    const int i0   = row0 & (N_-1), i1 = i0+1;
    const int tid  = threadIdx.x;
    const int warp = tid>>5, lane = tid&31;

    sq0[tid] = g_q[(size_t)row0*D_+tid];
    sq1[tid] = g_q[(size_t)row1*D_+tid];
    const float* cb = coords + (size_t)b*N_*3;
    for(int t=tid; t<N_*3; t+=128) scoord[t]=cb[t];
    __syncthreads();

    const float c00=scoord[i0*3+0], c01=scoord[i0*3+1], c02=scoord[i0*3+2];
    const float c10=scoord[i1*3+0], c11=scoord[i1*3+1], c12=scoord[i1*3+2];

    // ---- dists for both rows ----
    for(int j=tid; j<N_; j+=128){
        float x=scoord[j*3+0], y=scoord[j*3+1], z=scoord[j*3+2];
        float dx0=c00-x, dy0=c01-y, dz0=c02-z;
        float dx1=c10-x, dy1=c11-y, dz1=c12-z;
        float d0 = sqrtf(fmaf(dx0,dx0,fmaf(dy0,dy0,dz0*dz0)));
        float d1 = sqrtf(fmaf(dx1,dx1,fmaf(dy1,dy1,dz1*dz1)));
        sdist0[j]=d0; sdist1[j]=d1;
        srd0[j]=__fdividef(1.0f, fmaxf(d0,1e-6f));
        srd1[j]=__fdividef(1.0f, fmaxf(d1,1e-6f));
    }
    // ---- qc: 12 dots per row ----
    for(int m=warp; m<12; m+=4){
        float a0=0.f, a1=0.f;
        #pragma unroll
        for(int c=0;c<4;c++){
            int d = lane + 32*c;
            float w = g_Wc[d*12+m];
            a0 = fmaf(sq0[d], w, a0);
            a1 = fmaf(sq1[d], w, a1);
        }
        #pragma unroll
        for(int o=16;o;o>>=1){
            a0 += __shfl_down_sync(0xffffffffu, a0, o);
            a1 += __shfl_down_sync(0xffffffffu, a1, o);
        }
        if(lane==0){ sQC0[m]=a0; sQC1[m]=a1; }
    }
    __syncthreads();

    const float biasv0 = sQC0[0] + sQC0[11];
    const float biasv1 = sQC1[0] + sQC1[11];
    float qcr0[10], qcr1[10];
    #pragma unroll
    for(int p=0;p<10;p++){ qcr0[p]=sQC0[p+1]; qcr1[p]=sQC1[p+1]; }

    const __half2* khb = g_kh + (size_t)b*(D_/2)*N_;
    const __half2* vhb = g_vh + (size_t)b*N_*(D_/2);
    const float*  vecb = vector + (size_t)b*N_*3*V_;

    // ---- pass 1: lane = j, 4 chunks, both rows per k load ----
    float M0[11], M1[11];
    #pragma unroll
    for(int m=0;m<11;m++){ M0[m]=0.f; M1[m]=0.f; }

    #pragma unroll
    for(int chunk=0; chunk<4; chunk++){
        const int j = warp*32 + lane + chunk*128;
        const __half2* kcol = khb + j;
        float a0=0.f,b0=0.f,a1=0.f,b1=0.f;
        #pragma unroll 8
        for(int u=0; u<D_/2; u+=2){
            float2 ka = __half22float2(kcol[(size_t)(u+0)*N_]);
            float2 kc = __half22float2(kcol[(size_t)(u+1)*N_]);
            float4 q0 = *(const float4*)(sq0 + 2*u);
            float4 q1 = *(const float4*)(sq1 + 2*u);
            a0=fmaf(q0.x,ka.x,a0); b0=fmaf(q0.y,ka.y,b0);
            a0=fmaf(q0.z,kc.x,a0); b0=fmaf(q0.w,kc.y,b0);
            a1=fmaf(q1.x,ka.x,a1); b1=fmaf(q1.y,ka.y,b1);
            a1=fmaf(q1.z,kc.x,a1); b1=fmaf(q1.w,kc.y,b1);
        }
        const float dist0=sdist0[j], dist1=sdist1[j];
        float pol0 = qcr0[9];
        float pol1 = qcr1[9];
        #pragma unroll
        for(int p=8;p>=0;p--){
            pol0 = fmaf(pol0, dist0, qcr0[p]);
            pol1 = fmaf(pol1, dist1, qcr1[p]);
        }
        float e0 = __expf(fmaf(pol0, dist0, (a0+b0)+biasv0));
        float e1 = __expf(fmaf(pol1, dist1, (a1+b1)+biasv1));
        slog0[j]=e0; slog1[j]=e1;
        M0[10]+=e0; M1[10]+=e1;
        float t0=dist0, t1=dist1;
        #pragma unroll
        for(int p=0;p<10;p++){
            M0[p]=fmaf(e0,t0,M0[p]); t0*=dist0;
            M1[p]=fmaf(e1,t1,M1[p]); t1*=dist1;
        }
    }
    #pragma unroll
    for(int o=16;o;o>>=1){
        #pragma unroll
        for(int m=0;m<11;m++){
            M0[m] += __shfl_down_sync(0xffffffffu, M0[m], o);
            M1[m] += __shfl_down_sync(0xffffffffu, M1[m], o);
        }
    }
    if(lane==0){
        #pragma unroll
        for(int m=0;m<11;m++){ sMm0[warp][m]=M0[m]; sMm1[warp][m]=M1[m]; }
    }
    __syncthreads();
    if(tid<11) sMtot0[tid]=(sMm0[0][tid]+sMm0[1][tid])+(sMm0[2][tid]+sMm0[3][tid]);
    else if(tid>=16 && tid<27){ int m=tid-16; sMtot1[m]=(sMm1[0][m]+sMm1[1][m])+(sMm1[2][m]+sMm1[3][m]); }
    __syncthreads();
    const float inv0 = 1.0f/sMtot0[10];
    const float inv1 = 1.0f/sMtot1[10];
    if(tid<10) sMn0[tid]=sMtot0[tid]*inv0;
    else if(tid>=16 && tid<26) sMn1[tid-16]=sMtot1[tid-16]*inv1;
    // normalize slog in place
    for(int j=tid;j<N_;j+=128){ slog0[j]*=inv0; slog1[j]*=inv1; }
    __syncthreads();

    // ---- pass 2: V accumulation, both rows per v load ----
    {
        const int u = tid & 63, jh = tid >> 6;
        const int j0 = jh*256;
        float a0=0.f,a1=0.f,c0=0.f,c1=0.f;
        #pragma unroll 8
        for(int jj=0; jj<256; jj++){
            const int j = j0+jj;
            float2 vf = __half22float2(vhb[(size_t)j*(D_/2)+u]);
            float e0 = slog0[j], e1 = slog1[j];
            a0 = fmaf(e0, vf.x, a0); a1 = fmaf(e0, vf.y, a1);
            c0 = fmaf(e1, vf.x, c0); c1 = fmaf(e1, vf.y, c1);
        }
        sVp0[jh][2*u]=a0; sVp0[jh][2*u+1]=a1;
        sVp1[jh][2*u]=c0; sVp1[jh][2*u+1]=c1;
    }
    __syncthreads();

    // ---- vector agg (96 thr, both rows) + direction (24 thr) ----
    if(tid < 96){
        const int jh = tid/48, t48 = tid - jh*48;
        const int j0 = jh*256;
        float a0=0.f,a1=0.f;
        #pragma unroll 4
        for(int jj=0;jj<256;jj++){
            const int j=j0+jj;
            float v = vecb[(size_t)j*48+t48];
            a0 = fmaf(slog0[j], v, a0);
            a1 = fmaf(slog1[j], v, a1);
        }
        svaggp0[tid]=a0; svaggp1[tid]=a1;
    } else if(tid < 120){
        const int idx = tid-96;           // 0..23
        const int r = idx/12, rem = idx - r*12;
        const int c = rem>>2, g = rem&3;
        const float* sl = r? slog1 : slog0;
        const float* sr = r? srd1  : srd0;
        const float cic = r ? ((c==0)?c10:((c==1)?c11:c12))
                            : ((c==0)?c00:((c==1)?c01:c02));
        float acc=0.f;
        for(int j=g;j<N_;j+=4){
            acc = fmaf(sl[j]*sr[j], cic - scoord[j*3+c], acc);
        }
        sdirp[r][rem]=acc;
    }
    __syncthreads();
    if(tid<48){ svagg0[tid]=svaggp0[tid]+svaggp0[tid+48]; svagg1[tid]=svaggp1[tid]+svaggp1[tid+48]; }
    if(tid>=64 && tid<70){
        const int idx=tid-64, r=idx/3, c=idx-r*3;
        float a = (sdirp[r][c*4+0]+sdirp[r][c*4+1])+(sdirp[r][c*4+2]+sdirp[r][c*4+3]);
        if(r) sdir1[c]=a; else sdir0[c]=a;
    }

    // ---- Vd + H reconstruction (both rows, coeffs computed once) ----
    const float Vd0 = sVp0[0][tid]+sVp0[1][tid];
    const float Vd1 = sVp1[0][tid]+sVp1[1][tid];
    {
        float C[11];
        gelu_coeffs(w_d1[tid], b_d1[tid], C);
        float h0=C[0], h1=C[0];
        #pragma unroll
        for(int p=1;p<11;p++){
            h0 = fmaf(C[p], sMn0[p-1], h0);
            h1 = fmaf(C[p], sMn1[p-1], h1);
        }
        sH0[tid]=h0; sH1[tid]=h1;
    }
    __syncthreads();

    // ---- upd = attn@v + H@w_d2 + b_d2 (weights loaded once, 2 rows) ----
    {
        float u00=0,u01=0,u10=0,u11=0;
        #pragma unroll 4
        for(int e=0;e<D_;e+=2){
            float w0=w_d2[(e+0)*D_+tid], w1=w_d2[(e+1)*D_+tid];
            u00=fmaf(sH0[e+0],w0,u00); u10=fmaf(sH1[e+0],w0,u10);
            u01=fmaf(sH0[e+1],w1,u01); u11=fmaf(sH1[e+1],w1,u11);
        }
        float bd=b_d2[tid];
        sbuf0[tid]=Vd0+bd+(u00+u01);
        sbuf1[tid]=Vd1+bd+(u10+u11);
    }
    __syncthreads();

    // ---- scalar1 = scalar + upd@w_o + b_o ----
    float s10, s11;
    {
        float u00=0,u01=0,u10=0,u11=0;
        #pragma unroll 4
        for(int e=0;e<D_;e+=2){
            float w0=w_o[(e+0)*D_+tid], w1=w_o[(e+1)*D_+tid];
            u00=fmaf(sbuf0[e+0],w0,u00); u10=fmaf(sbuf1[e+0],w0,u10);
            u01=fmaf(sbuf0[e+1],w1,u01); u11=fmaf(sbuf1[e+1],w1,u11);
        }
        float bo=b_o[tid];
        s10 = scalar[(size_t)row0*D_+tid] + bo + (u00+u01);
        s11 = scalar[(size_t)row1*D_+tid] + bo + (u10+u11);
        sscal0[tid]=s10; sscal1[tid]=s11;
    }

    // ---- LN (both rows at once) ----
    {
        float m0=s10, m1=s11;
        blockSum2(m0,m1,red);
        m0*=(1.0f/D_); m1*=(1.0f/D_);
        float d0=s10-m0, d1=s11-m1;
        float v0=d0*d0, v1=d1*d1;
        blockSum2(v0,v1,red);
        float r0=rsqrtf(v0*(1.0f/D_)+1e-5f), r1=rsqrtf(v1*(1.0f/D_)+1e-5f);
        float gs=g_s[tid], bs=be_s[tid];
        shn0[tid]=d0*r0*gs+bs;
        shn1[tid]=d1*r1*gs+bs;
    }
    __syncthreads();

    // ---- FFN layer 1: 2 outputs x 2 rows per thread, weights once ----
    {
        float f00=0,f01=0,f10=0,f11=0;
        #pragma unroll 4
        for(int e=0;e<D_;e++){
            float wa=w_f1[e*2*D_+tid], wb=w_f1[e*2*D_+tid+128];
            float h0=shn0[e], h1=shn1[e];
            f00=fmaf(h0,wa,f00); f01=fmaf(h0,wb,f01);
            f10=fmaf(h1,wa,f10); f11=fmaf(h1,wb,f11);
        }
        float ba=b_f1[tid], bb=b_f1[tid+128];
        sf0[tid]    =geluf(ba+f00); sf0[tid+128]=geluf(bb+f01);
        sf1[tid]    =geluf(ba+f10); sf1[tid+128]=geluf(bb+f11);
    }
    __syncthreads();

    // ---- FFN layer 2 (K=256, weights once) ----
    {
        float u00=0,u01=0,u10=0,u11=0;
        #pragma unroll 4
        for(int e=0;e<2*D_;e+=2){
            float w0=w_f2[(e+0)*D_+tid], w1=w_f2[(e+1)*D_+tid];
            u00=fmaf(sf0[e+0],w0,u00); u10=fmaf(sf1[e+0],w0,u10);
            u01=fmaf(sf0[e+1],w1,u01); u11=fmaf(sf1[e+1],w1,u11);
        }
        float bf=b_f2[tid];
        float s20 = sscal0[tid] + bf + (u00+u01);
        float s21 = sscal1[tid] + bf + (u10+u11);
        out_scalar[(size_t)row0*D_+tid] = s20;
        out_scalar[(size_t)row1*D_+tid] = s21;
        __syncthreads();
        sscal0[tid]=s20; sscal1[tid]=s21;
    }
    __syncthreads();

    // ---- gate (both rows) ----
    if(tid<V_){
        float g0=0,g1=0;
        #pragma unroll 4
        for(int d2=0;d2<D_;d2++){
            float w = w_g[d2*V_+tid];
            g0 = fmaf(sscal0[d2], w, g0);
            g1 = fmaf(sscal1[d2], w, g1);
        }
        float bgv=b_g[tid];
        sgate0[tid]=1.0f/(1.0f+__expf(-(g0+bgv)));
        sgate1[tid]=1.0f/(1.0f+__expf(-(g1+bgv)));
    }
    __syncthreads();

    // ---- agg, LN over V, proj, vector residual (both rows) ----
    if(tid<48){
        int c = tid>>4, vv = tid&15;
        sagg0[tid] = svagg0[tid] + sdir0[c]*sgate0[vv];
        sagg1[tid] = svagg1[tid] + sdir1[c]*sgate1[vv];
    }
    __syncthreads();
    if(tid<48){
        int c = tid>>4, vv = tid&15;
        #pragma unroll
        for(int r=0;r<2;r++){
            const float* sagg = r? sagg1 : sagg0;
            float m2=0.0f;
            #pragma unroll
            for(int u=0;u<V_;u++) m2 += sagg[c*V_+u];
            m2 *= (1.0f/V_);
            float var2=0.0f;
            #pragma unroll
            for(int u=0;u<V_;u++){ float d3=sagg[c*V_+u]-m2; var2 += d3*d3; }
            var2 *= (1.0f/V_);
            float invr = rsqrtf(var2+1e-5f);
            float acc = b_vo[vv];
            #pragma unroll
            for(int u=0;u<V_;u++){
                float lnu = (sagg[c*V_+u]-m2)*invr*g_v_[u] + be_v[u];
                acc = fmaf(lnu, w_vo[u*V_+vv], acc);
            }
            const int ii = r? i1 : i0;
            const int rr = r? row1 : row0;
            out_vector[(size_t)rr*3*V_+tid] = vecb[(size_t)ii*3*V_+tid] + acc;
        }
    }
}

extern "C" void kernel_launch(void* const* d_in, const int* in_sizes, int n_in,
                              void* d_out, int out_size)
{
    const float* scalar = (const float*)d_in[0];
    const float* vector = (const float*)d_in[1];
    const float* coords = (const float*)d_in[2];
    const float* w_q  = (const float*)d_in[3];  const float* b_q  = (const float*)d_in[4];
    const float* w_k  = (const float*)d_in[5];  const float* b_k  = (const float*)d_in[6];
    const float* w_v  = (const float*)d_in[7];  const float* b_v  = (const float*)d_in[8];
    const float* w_d1 = (const float*)d_in[9];  const float* b_d1 = (const float*)d_in[10];
    const float* w_d2 = (const float*)d_in[11]; const float* b_d2 = (const float*)d_in[12];
    const float* w_g  = (const float*)d_in[13]; const float* b_g  = (const float*)d_in[14];
    const float* w_o  = (const float*)d_in[15]; const float* b_o  = (const float*)d_in[16];
    const float* w_f1 = (const float*)d_in[17]; const float* b_f1 = (const float*)d_in[18];
    const float* w_f2 = (const float*)d_in[19]; const float* b_f2 = (const float*)d_in[20];
    const float* w_vo = (const float*)d_in[21]; const float* b_vo = (const float*)d_in[22];
    const float* g_s  = (const float*)d_in[23]; const float* be_s = (const float*)d_in[24];
    const float* g_v  = (const float*)d_in[25]; const float* be_v = (const float*)d_in[26];

    float* out = (float*)d_out;
    float* out_scalar = out;
    float* out_vector = out + (size_t)ROWS*D_;

    prep_kernel<<<ROWS/4 + 1,128>>>(scalar, w_q,b_q, w_k,b_k, w_v,b_v,
                                    w_d1,b_d1, w_d2,b_d2, g_s,be_s);
    main_kernel<<<ROWS/2,128>>>(scalar, vector, coords,
                              w_d1,b_d1, w_d2,b_d2, w_g,b_g, w_o,b_o,
                              w_f1,b_f1, w_f2,b_f2, w_vo,b_vo,
                              g_s,be_s, g_v,be_v,
                              out_scalar, out_vector);
}